// round 1
// baseline (speedup 1.0000x reference)
#include <cuda_runtime.h>
#include <math.h>

#define B_     8
#define C_     512
#define HH     64
#define WW     64
#define NPIX   4096
#define HEADS_ 8
#define HD     64

// ---------------- scratch (allocation-free: __device__ globals) ----------------
__device__ float g_y [B_ * C_ * NPIX];   // dwconv output
__device__ float g_q [B_ * C_ * NPIX];
__device__ float g_k [B_ * C_ * NPIX];
__device__ float g_v [B_ * C_ * NPIX];
__device__ float g_ao[B_ * C_ * NPIX];   // attention output (pre-proj)
__device__ float g_attn[B_ * HEADS_ * HD * HD];
__device__ float g_rq[B_ * C_];
__device__ float g_rk[B_ * C_];
__device__ float g_rv[B_ * C_];

// ---------------- depthwise 3x3, padding 1 ----------------
__global__ __launch_bounds__(256) void dwconv_kernel(const float* __restrict__ x,
                                                     const float* __restrict__ w) {
    int plane = blockIdx.y;                 // b*C + c
    int c = plane & (C_ - 1);
    __shared__ float ws[9];
    if (threadIdx.x < 9) ws[threadIdx.x] = w[c * 9 + threadIdx.x];
    __syncthreads();
    int p = blockIdx.x * 256 + threadIdx.x; // 0..4095
    int h = p >> 6, wc = p & 63;
    const float* xp = x + (size_t)plane * NPIX;
    float acc = 0.f;
#pragma unroll
    for (int kh = 0; kh < 3; kh++) {
        int hh = h + kh - 1;
        if (hh < 0 || hh >= HH) continue;
#pragma unroll
        for (int kw = 0; kw < 3; kw++) {
            int wcol = wc + kw - 1;
            if (wcol < 0 || wcol >= WW) continue;
            acc = fmaf(ws[kh * 3 + kw], xp[hh * WW + wcol], acc);
        }
    }
    g_y[(size_t)plane * NPIX + p] = acc;
}

// ---------------- batched SGEMM: C[b] = A(weight [M,K]) * B[b] ([K,N]) ----------------
#define BM 128
#define BN 128
#define BK 16
#define TM 8
#define TN 8

__global__ __launch_bounds__(256) void gemm_bcast_kernel(const float* __restrict__ A,
                                                         const float* __restrict__ Bm,
                                                         float* __restrict__ Cm,
                                                         int M, int N, int K) {
    __shared__ float As[BK][BM + 4];
    __shared__ float Bs[BK][BN];
    int batch = blockIdx.z;
    const float* Bp = Bm + (size_t)batch * K * N;
    float* Cp = Cm + (size_t)batch * M * N;
    int bm = blockIdx.y * BM;
    int bn = blockIdx.x * BN;
    int tid = threadIdx.x;
    int arow = tid >> 2;             // 0..63
    int acol = (tid & 3) << 2;       // 0,4,8,12
    int brow = tid >> 5;             // 0..7
    int bcol = (tid & 31) << 2;      // 0..124
    int tr = (tid >> 4) * TM;
    int tc = (tid & 15) * TN;
    float acc[TM][TN] = {};

    for (int k0 = 0; k0 < K; k0 += BK) {
#pragma unroll
        for (int i = 0; i < 2; i++) {
            int r = arow + i * 64;
            float4 av = *(const float4*)&A[(size_t)(bm + r) * K + k0 + acol];
            As[acol + 0][r] = av.x;
            As[acol + 1][r] = av.y;
            As[acol + 2][r] = av.z;
            As[acol + 3][r] = av.w;
        }
#pragma unroll
        for (int i = 0; i < 2; i++) {
            int r = brow + i * 8;
            *(float4*)&Bs[r][bcol] = *(const float4*)&Bp[(size_t)(k0 + r) * N + bn + bcol];
        }
        __syncthreads();
#pragma unroll
        for (int kk = 0; kk < BK; kk++) {
            float ar[TM], br[TN];
            *(float4*)&ar[0] = *(float4*)&As[kk][tr];
            *(float4*)&ar[4] = *(float4*)&As[kk][tr + 4];
            *(float4*)&br[0] = *(float4*)&Bs[kk][tc];
            *(float4*)&br[4] = *(float4*)&Bs[kk][tc + 4];
#pragma unroll
            for (int i = 0; i < TM; i++)
#pragma unroll
                for (int j = 0; j < TN; j++)
                    acc[i][j] = fmaf(ar[i], br[j], acc[i][j]);
        }
        __syncthreads();
    }
#pragma unroll
    for (int i = 0; i < TM; i++) {
#pragma unroll
        for (int j = 0; j < TN; j += 4) {
            float4 o = make_float4(acc[i][j], acc[i][j + 1], acc[i][j + 2], acc[i][j + 3]);
            *(float4*)&Cp[(size_t)(bm + tr + i) * N + bn + tc + j] = o;
        }
    }
}

// ---------------- reciprocal L2 norms of q/k/v rows (per b,c over N=4096) ----------------
__global__ __launch_bounds__(256) void rnorm_kernel() {
    int idx = blockIdx.x;
    int which = idx >> 12;           // 4096 rows per tensor
    int row = idx & 4095;
    const float* src = (which == 0) ? g_q : (which == 1) ? g_k : g_v;
    float* dst = (which == 0) ? g_rq : (which == 1) ? g_rk : g_rv;
    const float* p = src + (size_t)row * NPIX;
    float s = 0.f;
    for (int i = threadIdx.x * 4; i < NPIX; i += 1024) {
        float4 t = *(const float4*)&p[i];
        s += t.x * t.x + t.y * t.y + t.z * t.z + t.w * t.w;
    }
#pragma unroll
    for (int off = 16; off; off >>= 1) s += __shfl_xor_sync(0xffffffffu, s, off);
    __shared__ float red[8];
    int warp = threadIdx.x >> 5, lane = threadIdx.x & 31;
    if (lane == 0) red[warp] = s;
    __syncthreads();
    if (threadIdx.x == 0) {
        float t = 0.f;
#pragma unroll
        for (int i = 0; i < 8; i++) t += red[i];
        dst[row] = 1.0f / fmaxf(sqrtf(t), 1e-12f);
    }
}

// ---------------- attention scores (64x64 over K=4096) + softmax, rv folded in ----------------
__global__ __launch_bounds__(256) void attn_scores_kernel() {
    int bh = blockIdx.x;             // 0..63
    int b = bh >> 3, hg = bh & 7;
    size_t base = ((size_t)b * C_ + hg * HD) * (size_t)NPIX;
    const float* qb = g_q + base;
    const float* kb = g_k + base;
    __shared__ float Qs[HD][37];
    __shared__ float Kst[32][65];
    __shared__ float Ss[HD][HD];
    int tid = threadIdx.x;
    int tx = tid & 15, ty = tid >> 4;
    int lrow = tid >> 3;             // 0..31
    int lcol = (tid & 7) << 2;       // 0..28
    float acc[4][4] = {};

    for (int n0 = 0; n0 < NPIX; n0 += 32) {
#pragma unroll
        for (int pp = 0; pp < 2; pp++) {
            int d = lrow + pp * 32;
            float4 qv = *(const float4*)&qb[(size_t)d * NPIX + n0 + lcol];
            Qs[d][lcol + 0] = qv.x; Qs[d][lcol + 1] = qv.y;
            Qs[d][lcol + 2] = qv.z; Qs[d][lcol + 3] = qv.w;
            float4 kv = *(const float4*)&kb[(size_t)d * NPIX + n0 + lcol];
            Kst[lcol + 0][d] = kv.x; Kst[lcol + 1][d] = kv.y;
            Kst[lcol + 2][d] = kv.z; Kst[lcol + 3][d] = kv.w;
        }
        __syncthreads();
#pragma unroll
        for (int kk = 0; kk < 32; kk++) {
            float ar[4], br[4];
#pragma unroll
            for (int i = 0; i < 4; i++) ar[i] = Qs[ty * 4 + i][kk];
#pragma unroll
            for (int j = 0; j < 4; j++) br[j] = Kst[kk][tx * 4 + j];
#pragma unroll
            for (int i = 0; i < 4; i++)
#pragma unroll
                for (int j = 0; j < 4; j++)
                    acc[i][j] = fmaf(ar[i], br[j], acc[i][j]);
        }
        __syncthreads();
    }

    const float scale = 0.125f;      // HEAD_DIM^-0.5
    int cb = b * C_ + hg * HD;
#pragma unroll
    for (int i = 0; i < 4; i++) {
        float rqv = g_rq[cb + ty * 4 + i] * scale;
#pragma unroll
        for (int j = 0; j < 4; j++)
            Ss[ty * 4 + i][tx * 4 + j] = acc[i][j] * rqv * g_rk[cb + tx * 4 + j];
    }
    __syncthreads();

    int warp = tid >> 5, lane = tid & 31;
#pragma unroll
    for (int rr = 0; rr < 8; rr++) {
        int r = warp * 8 + rr;
        float v0 = Ss[r][lane], v1 = Ss[r][lane + 32];
        float m = fmaxf(v0, v1);
#pragma unroll
        for (int off = 16; off; off >>= 1) m = fmaxf(m, __shfl_xor_sync(0xffffffffu, m, off));
        float e0 = __expf(v0 - m), e1 = __expf(v1 - m);
        float s = e0 + e1;
#pragma unroll
        for (int off = 16; off; off >>= 1) s += __shfl_xor_sync(0xffffffffu, s, off);
        float inv = 1.0f / s;
        g_attn[(size_t)bh * 4096 + r * 64 + lane]      = e0 * inv * g_rv[cb + lane];
        g_attn[(size_t)bh * 4096 + r * 64 + lane + 32] = e1 * inv * g_rv[cb + lane + 32];
    }
}

// ---------------- out = attn @ v  (64x64 @ 64x4096, tiled over n) ----------------
__global__ __launch_bounds__(256) void attn_apply_kernel() {
    int nt = blockIdx.x;             // 0..31 (128-wide n tiles)
    int bh = blockIdx.y;             // 0..63
    int b = bh >> 3, hg = bh & 7;
    __shared__ float As[HD * HD];    // 16 KB
    __shared__ float Vs[HD][128];    // 32 KB
    int tid = threadIdx.x;

    for (int i = tid * 4; i < HD * HD; i += 1024)
        *(float4*)&As[i] = *(const float4*)&g_attn[(size_t)bh * 4096 + i];

    const float* vb = g_v + ((size_t)b * C_ + hg * HD) * NPIX + nt * 128;
    int vr = tid >> 5;               // 0..7
    int vc = (tid & 31) << 2;        // 0..124
#pragma unroll
    for (int pp = 0; pp < 8; pp++) {
        int e = vr + pp * 8;
        *(float4*)&Vs[e][vc] = *(const float4*)&vb[(size_t)e * NPIX + vc];
    }
    __syncthreads();

    int nloc = tid & 127;
    int dbase = (tid >> 7) * 32;     // 0 or 32
    float acc[32] = {};
#pragma unroll
    for (int e = 0; e < 64; e++) {
        float vv = Vs[e][nloc];
#pragma unroll
        for (int dd = 0; dd < 32; dd++)
            acc[dd] = fmaf(As[(dbase + dd) * 64 + e], vv, acc[dd]);
    }
    float* ob = g_ao + ((size_t)b * C_ + hg * HD) * NPIX + nt * 128;
#pragma unroll
    for (int dd = 0; dd < 32; dd++)
        ob[(size_t)(dbase + dd) * NPIX + nloc] = acc[dd];
}

// ---------------- launch ----------------
extern "C" void kernel_launch(void* const* d_in, const int* in_sizes, int n_in,
                              void* d_out, int out_size) {
    const float* x  = (const float*)d_in[0];
    const float* dw = (const float*)d_in[1];
    const float* qw = (const float*)d_in[2];
    const float* kw = (const float*)d_in[3];
    const float* vw = (const float*)d_in[4];
    const float* pw = (const float*)d_in[5];
    float* out = (float*)d_out;

    float *yp, *qp, *kp, *vp, *aop;
    cudaGetSymbolAddress((void**)&yp,  g_y);
    cudaGetSymbolAddress((void**)&qp,  g_q);
    cudaGetSymbolAddress((void**)&kp,  g_k);
    cudaGetSymbolAddress((void**)&vp,  g_v);
    cudaGetSymbolAddress((void**)&aop, g_ao);

    dwconv_kernel<<<dim3(NPIX / 256, B_ * C_), 256>>>(x, dw);

    dim3 ggrid(NPIX / BN, C_ / BM, B_);
    gemm_bcast_kernel<<<ggrid, 256>>>(qw, yp, qp, C_, NPIX, C_);
    gemm_bcast_kernel<<<ggrid, 256>>>(kw, yp, kp, C_, NPIX, C_);
    gemm_bcast_kernel<<<ggrid, 256>>>(vw, yp, vp, C_, NPIX, C_);

    rnorm_kernel<<<3 * B_ * C_, 256>>>();
    attn_scores_kernel<<<B_ * HEADS_, 256>>>();
    attn_apply_kernel<<<dim3(NPIX / 128, B_ * HEADS_), 256>>>();

    gemm_bcast_kernel<<<ggrid, 256>>>(pw, aop, out, C_, NPIX, C_);
}

// round 4
// speedup vs baseline: 2.4085x; 2.4085x over previous
#include <cuda_runtime.h>
#include <cuda_bf16.h>
#include <math.h>
#include <stdint.h>

#define B_     8
#define C_     512
#define HH     64
#define WW     64
#define NPIX   4096
#define HEADS_ 8
#define HD     64
#define TOFF   (B_ * C_ * NPIX)      // per-tensor offset in g_qkv

// ---------------- scratch ----------------
__device__ __align__(16) float g_qkv[3 * TOFF];                 // q,k,v fp32
__device__ __align__(16) __nv_bfloat16 g_yh[TOFF], g_yl[TOFF];  // dwconv out, bf16 split
__device__ __align__(16) __nv_bfloat16 g_aoh[TOFF], g_aol[TOFF];
__device__ __align__(16) __nv_bfloat16 g_wh[4 * C_ * C_], g_wl[4 * C_ * C_];
__device__ float g_attn[B_ * HEADS_ * HD * HD];
__device__ float g_part[B_ * HEADS_ * 8 * HD * HD];
__device__ float g_rq[B_ * C_];
__device__ float g_rk[B_ * C_];
__device__ float g_rv[B_ * C_];

// ---------------- PTX helpers (baseline sm_80+ features only) ----------------
__device__ __forceinline__ uint32_t smem_u32(const void* p) {
    uint32_t a;
    asm("{ .reg .u64 t; cvta.to.shared.u64 t, %1; cvt.u32.u64 %0, t; }" : "=r"(a) : "l"(p));
    return a;
}
#define CP16(s, g) asm volatile("cp.async.cg.shared.global [%0], [%1], 16;" :: "r"(s), "l"(g))
#define CP_COMMIT() asm volatile("cp.async.commit_group;" ::: "memory")
#define CP_WAIT1()  asm volatile("cp.async.wait_group 1;" ::: "memory")

#define LDSM_X4(r, a) \
    asm volatile("ldmatrix.sync.aligned.m8n8.x4.shared.b16 {%0,%1,%2,%3}, [%4];" \
        : "=r"((r)[0]), "=r"((r)[1]), "=r"((r)[2]), "=r"((r)[3]) : "r"(a))
#define LDSM_X4T(r, a) \
    asm volatile("ldmatrix.sync.aligned.m8n8.x4.trans.shared.b16 {%0,%1,%2,%3}, [%4];" \
        : "=r"((r)[0]), "=r"((r)[1]), "=r"((r)[2]), "=r"((r)[3]) : "r"(a))
#define MMA16816(d, a, b0, b1) \
    asm volatile("mma.sync.aligned.m16n8k16.row.col.f32.bf16.bf16.f32 " \
        "{%0,%1,%2,%3}, {%4,%5,%6,%7}, {%8,%9}, {%0,%1,%2,%3};" \
        : "+f"((d)[0]), "+f"((d)[1]), "+f"((d)[2]), "+f"((d)[3]) \
        : "r"((a)[0]), "r"((a)[1]), "r"((a)[2]), "r"((a)[3]), "r"(b0), "r"(b1))

__device__ __forceinline__ uint32_t sw128(uint32_t o) { return o ^ ((o >> 3) & 0x70); }

__device__ __forceinline__ void split_f(float v, __nv_bfloat16& hi, __nv_bfloat16& lo) {
    hi = __float2bfloat16_rn(v);
    lo = __float2bfloat16_rn(v - __bfloat162float(hi));
}

// ---------------- depthwise 3x3 -> bf16 hi/lo ----------------
__global__ __launch_bounds__(256) void dwconv_kernel(const float* __restrict__ x,
                                                     const float* __restrict__ w) {
    int plane = blockIdx.y;
    int c = plane & (C_ - 1);
    __shared__ float ws[9];
    if (threadIdx.x < 9) ws[threadIdx.x] = w[c * 9 + threadIdx.x];
    __syncthreads();
    int p = blockIdx.x * 256 + threadIdx.x;
    int h = p >> 6, wc = p & 63;
    const float* xp = x + (size_t)plane * NPIX;
    float acc = 0.f;
#pragma unroll
    for (int kh = 0; kh < 3; kh++) {
        int hh = h + kh - 1;
        if (hh < 0 || hh >= HH) continue;
#pragma unroll
        for (int kw = 0; kw < 3; kw++) {
            int wcol = wc + kw - 1;
            if (wcol < 0 || wcol >= WW) continue;
            acc = fmaf(ws[kh * 3 + kw], xp[hh * WW + wcol], acc);
        }
    }
    __nv_bfloat16 hi, lo;
    split_f(acc, hi, lo);
    g_yh[(size_t)plane * NPIX + p] = hi;
    g_yl[(size_t)plane * NPIX + p] = lo;
}

// ---------------- weight conversion: stacked [q;k;v;proj] -> bf16 hi/lo ----------------
__global__ __launch_bounds__(256) void convert_w_kernel(const float* __restrict__ qw,
                                                        const float* __restrict__ kw,
                                                        const float* __restrict__ vw,
                                                        const float* __restrict__ pw) {
    int idx = blockIdx.x * 256 + threadIdx.x;     // 0 .. 4*262144-1
    int m = idx >> 18;
    const float* src = (m == 0) ? qw : (m == 1) ? kw : (m == 2) ? vw : pw;
    float v = src[idx & 262143];
    __nv_bfloat16 hi, lo;
    split_f(v, hi, lo);
    g_wh[idx] = hi;
    g_wl[idx] = lo;
}

// ---------------- bf16 HMMA GEMM: C = W[M,512] x Y[b][512,4096], 3x split ----------------
// CTA tile 128x128, K chunk 64 (128B rows, SW128), double-buffered cp.async.
#define A_HI 0
#define A_LO 16384
#define B_HI 32768
#define B_LO 49152
#define STAGE 65536
#define GEMM_SMEM (2 * STAGE)

__global__ __launch_bounds__(256, 1) void gemm_hmma_kernel(const __nv_bfloat16* __restrict__ Wh,
                                                           const __nv_bfloat16* __restrict__ Wl,
                                                           const __nv_bfloat16* __restrict__ Bhg,
                                                           const __nv_bfloat16* __restrict__ Blg,
                                                           float* __restrict__ Cout,
                                                           int qkv_mode) {
    extern __shared__ char smem[];
    uint32_t sb = smem_u32(smem);
    int tid = threadIdx.x;
    int l = tid & 31, wid = tid >> 5;
    int wm = wid & 1, wn = wid >> 1;
    int bn = blockIdx.x * 128;
    int bm = blockIdx.y * 128;
    int bz = blockIdx.z;
    const __nv_bfloat16* Bh = Bhg + (size_t)bz * C_ * NPIX;
    const __nv_bfloat16* Bl = Blg + (size_t)bz * C_ * NPIX;

    // tile fills: A = 128 rows x 64 K (128B rows) = 1024 x 16B; B = 64 rows x 128 N = 1024 x 16B
    auto load_chunk = [&](int chunk, int stg) {
        uint32_t st = sb + stg * STAGE;
        int k0 = chunk * 64;
#pragma unroll
        for (int it = 0; it < 4; it++) {
            int idx = tid + it * 256;              // 0..1023
            // ---- A ----
            int ar = idx >> 3;                     // 0..127 (M row)
            int ac = (idx & 7) << 3;               // K element 0,8,..,56
            uint32_t aswo = sw128((uint32_t)(ar * 128 + ac * 2));
            const __nv_bfloat16* agh = Wh + (size_t)(bm + ar) * C_ + k0 + ac;
            const __nv_bfloat16* agl = Wl + (size_t)(bm + ar) * C_ + k0 + ac;
            CP16(st + A_HI + aswo, agh);
            CP16(st + A_LO + aswo, agl);
            // ---- B ----
            int brr = idx >> 4;                    // 0..63 (K row)
            int bnn = (idx & 15) << 3;             // N element 0,8,..,120
            int s = bnn >> 6, nl = bnn & 63;
            uint32_t bswo = (uint32_t)(s * 8192) + sw128((uint32_t)(brr * 128 + nl * 2));
            const __nv_bfloat16* bgh = Bh + (size_t)(k0 + brr) * NPIX + bn + bnn;
            const __nv_bfloat16* bgl = Bl + (size_t)(k0 + brr) * NPIX + bn + bnn;
            CP16(st + B_HI + bswo, bgh);
            CP16(st + B_LO + bswo, bgl);
        }
    };

    float acc[4][4][4] = {};
    int lr = l & 15;
    int lc = (l >> 4) << 4;   // 0 or 16 bytes

    load_chunk(0, 0); CP_COMMIT();
    load_chunk(1, 1); CP_COMMIT();

    for (int chunk = 0; chunk < 8; chunk++) {
        CP_WAIT1();
        __syncthreads();
        uint32_t st = sb + (chunk & 1) * STAGE;
#pragma unroll
        for (int k16 = 0; k16 < 4; k16++) {
            uint32_t ah[4][4], al[4][4], bh[2][4], bl[2][4];
            int kb = k16 * 32 + lc;
#pragma unroll
            for (int mt = 0; mt < 4; mt++) {
                uint32_t swo = sw128((uint32_t)((wm * 64 + mt * 16 + lr) * 128 + kb));
                LDSM_X4(ah[mt], st + A_HI + swo);
                LDSM_X4(al[mt], st + A_LO + swo);
            }
            uint32_t pb = (uint32_t)((wn >> 1) * 8192);
#pragma unroll
            for (int h = 0; h < 2; h++) {
                uint32_t swo = sw128((uint32_t)((k16 * 16 + lr) * 128 + (wn & 1) * 64 + h * 32 + lc));
                LDSM_X4T(bh[h], st + B_HI + pb + swo);
                LDSM_X4T(bl[h], st + B_LO + pb + swo);
            }
#pragma unroll
            for (int mt = 0; mt < 4; mt++) {
#pragma unroll
                for (int nt = 0; nt < 4; nt++) {
                    int h = nt >> 1, pr = (nt & 1) * 2;
                    MMA16816(acc[mt][nt], ah[mt], bh[h][pr], bh[h][pr + 1]);
                    MMA16816(acc[mt][nt], ah[mt], bl[h][pr], bl[h][pr + 1]);
                    MMA16816(acc[mt][nt], al[mt], bh[h][pr], bh[h][pr + 1]);
                }
            }
        }
        __syncthreads();
        if (chunk + 2 < 8) load_chunk(chunk + 2, chunk & 1);
        CP_COMMIT();
    }

    // epilogue: write fp32
    int l4 = l >> 2, l2 = (l & 3) << 1;
#pragma unroll
    for (int mt = 0; mt < 4; mt++) {
        int row0 = bm + wm * 64 + mt * 16 + l4;
#pragma unroll
        for (int half = 0; half < 2; half++) {
            int row = row0 + half * 8;
            float* base;
            if (qkv_mode) {
                int which = row >> 9, ml = row & 511;
                base = Cout + ((size_t)which * B_ + bz) * C_ * NPIX + (size_t)ml * NPIX;
            } else {
                base = Cout + ((size_t)bz * C_ + row) * NPIX;
            }
#pragma unroll
            for (int nt = 0; nt < 4; nt++) {
                int col = bn + wn * 32 + nt * 8 + l2;
                float2 v = make_float2(acc[mt][nt][half * 2], acc[mt][nt][half * 2 + 1]);
                *(float2*)(base + col) = v;
            }
        }
    }
}

// ---------------- reciprocal L2 norms over q/k/v rows ----------------
__global__ __launch_bounds__(256) void rnorm_kernel() {
    int idx = blockIdx.x;
    int which = idx >> 12;
    int row = idx & 4095;
    const float* p = g_qkv + (size_t)which * TOFF + (size_t)row * NPIX;
    float* dst = (which == 0) ? g_rq : (which == 1) ? g_rk : g_rv;
    float s = 0.f;
    for (int i = threadIdx.x * 4; i < NPIX; i += 1024) {
        float4 t = *(const float4*)&p[i];
        s += t.x * t.x + t.y * t.y + t.z * t.z + t.w * t.w;
    }
#pragma unroll
    for (int off = 16; off; off >>= 1) s += __shfl_xor_sync(0xffffffffu, s, off);
    __shared__ float red[8];
    int warp = threadIdx.x >> 5, lane = threadIdx.x & 31;
    if (lane == 0) red[warp] = s;
    __syncthreads();
    if (threadIdx.x == 0) {
        float t = 0.f;
#pragma unroll
        for (int i = 0; i < 8; i++) t += red[i];
        dst[row] = 1.0f / fmaxf(sqrtf(t), 1e-12f);
    }
}

// ---------------- attention scores: split-K partials ----------------
__global__ __launch_bounds__(256) void scores_part_kernel() {
    int sp = blockIdx.x;
    int bh = blockIdx.y;
    int b = bh >> 3, hg = bh & 7;
    size_t base = ((size_t)b * C_ + hg * HD) * (size_t)NPIX;
    const float* qb = g_qkv + base;
    const float* kb = g_qkv + TOFF + base;
    __shared__ float Qs[HD][37];
    __shared__ float Kst[32][65];
    int tid = threadIdx.x;
    int tx = tid & 15, ty = tid >> 4;
    int lrow = tid >> 3;
    int lcol = (tid & 7) << 2;
    float acc[4][4] = {};
    int nbeg = sp * 512;
    for (int n0 = nbeg; n0 < nbeg + 512; n0 += 32) {
#pragma unroll
        for (int pp = 0; pp < 2; pp++) {
            int d = lrow + pp * 32;
            float4 qv = *(const float4*)&qb[(size_t)d * NPIX + n0 + lcol];
            Qs[d][lcol + 0] = qv.x; Qs[d][lcol + 1] = qv.y;
            Qs[d][lcol + 2] = qv.z; Qs[d][lcol + 3] = qv.w;
            float4 kv = *(const float4*)&kb[(size_t)d * NPIX + n0 + lcol];
            Kst[lcol + 0][d] = kv.x; Kst[lcol + 1][d] = kv.y;
            Kst[lcol + 2][d] = kv.z; Kst[lcol + 3][d] = kv.w;
        }
        __syncthreads();
#pragma unroll
        for (int kk = 0; kk < 32; kk++) {
            float ar[4], br[4];
#pragma unroll
            for (int i = 0; i < 4; i++) ar[i] = Qs[ty * 4 + i][kk];
#pragma unroll
            for (int j = 0; j < 4; j++) br[j] = Kst[kk][tx * 4 + j];
#pragma unroll
            for (int i = 0; i < 4; i++)
#pragma unroll
                for (int j = 0; j < 4; j++)
                    acc[i][j] = fmaf(ar[i], br[j], acc[i][j]);
        }
        __syncthreads();
    }
    float* op = g_part + ((size_t)bh * 8 + sp) * 4096;
#pragma unroll
    for (int i = 0; i < 4; i++)
#pragma unroll
        for (int j = 0; j < 4; j++)
            op[(size_t)(ty * 4 + i) * 64 + tx * 4 + j] = acc[i][j];
}

// ---------------- reduce + softmax, fold rq/rk/rv ----------------
__global__ __launch_bounds__(256) void softmax_kernel() {
    int bh = blockIdx.x;
    int b = bh >> 3, hg = bh & 7;
    int cb = b * C_ + hg * HD;
    __shared__ float Ss[64][64];
    int tid = threadIdx.x;
    const float scale = 0.125f;
    for (int i = tid; i < 4096; i += 256) {
        float s = 0.f;
#pragma unroll
        for (int p = 0; p < 8; p++) s += g_part[((size_t)bh * 8 + p) * 4096 + i];
        int r = i >> 6, c = i & 63;
        Ss[r][c] = s * g_rq[cb + r] * scale * g_rk[cb + c];
    }
    __syncthreads();
    int warp = tid >> 5, lane = tid & 31;
#pragma unroll
    for (int rr = 0; rr < 8; rr++) {
        int r = warp * 8 + rr;
        float v0 = Ss[r][lane], v1 = Ss[r][lane + 32];
        float m = fmaxf(v0, v1);
#pragma unroll
        for (int off = 16; off; off >>= 1) m = fmaxf(m, __shfl_xor_sync(0xffffffffu, m, off));
        float e0 = __expf(v0 - m), e1 = __expf(v1 - m);
        float s = e0 + e1;
#pragma unroll
        for (int off = 16; off; off >>= 1) s += __shfl_xor_sync(0xffffffffu, s, off);
        float inv = 1.0f / s;
        g_attn[(size_t)bh * 4096 + r * 64 + lane]      = e0 * inv * g_rv[cb + lane];
        g_attn[(size_t)bh * 4096 + r * 64 + lane + 32] = e1 * inv * g_rv[cb + lane + 32];
    }
}

// ---------------- out = attn @ v -> bf16 hi/lo ----------------
__global__ __launch_bounds__(256) void attn_apply_kernel() {
    int nt = blockIdx.x;
    int bh = blockIdx.y;
    int b = bh >> 3, hg = bh & 7;
    __shared__ float As[HD * HD];
    __shared__ float Vs[HD][128];
    int tid = threadIdx.x;

    for (int i = tid * 4; i < HD * HD; i += 1024)
        *(float4*)&As[i] = *(const float4*)&g_attn[(size_t)bh * 4096 + i];

    const float* vb = g_qkv + 2 * (size_t)TOFF + ((size_t)b * C_ + hg * HD) * NPIX + nt * 128;
    int vr = tid >> 5;
    int vc = (tid & 31) << 2;
#pragma unroll
    for (int pp = 0; pp < 8; pp++) {
        int e = vr + pp * 8;
        *(float4*)&Vs[e][vc] = *(const float4*)&vb[(size_t)e * NPIX + vc];
    }
    __syncthreads();

    int nloc = tid & 127;
    int dbase = (tid >> 7) * 32;
    float acc[32] = {};
#pragma unroll
    for (int e = 0; e < 64; e++) {
        float vv = Vs[e][nloc];
#pragma unroll
        for (int dd = 0; dd < 32; dd++)
            acc[dd] = fmaf(As[(dbase + dd) * 64 + e], vv, acc[dd]);
    }
    size_t ob = ((size_t)b * C_ + hg * HD) * NPIX + nt * 128 + nloc;
#pragma unroll
    for (int dd = 0; dd < 32; dd++) {
        __nv_bfloat16 hi, lo;
        split_f(acc[dd], hi, lo);
        g_aoh[ob + (size_t)(dbase + dd) * NPIX] = hi;
        g_aol[ob + (size_t)(dbase + dd) * NPIX] = lo;
    }
}

// ---------------- launch ----------------
extern "C" void kernel_launch(void* const* d_in, const int* in_sizes, int n_in,
                              void* d_out, int out_size) {
    const float* x  = (const float*)d_in[0];
    const float* dw = (const float*)d_in[1];
    const float* qw = (const float*)d_in[2];
    const float* kw = (const float*)d_in[3];
    const float* vw = (const float*)d_in[4];
    const float* pw = (const float*)d_in[5];
    float* out = (float*)d_out;

    float* qkvp;
    __nv_bfloat16 *yhp, *ylp, *aohp, *aolp, *whp, *wlp;
    cudaGetSymbolAddress((void**)&qkvp, g_qkv);
    cudaGetSymbolAddress((void**)&yhp,  g_yh);
    cudaGetSymbolAddress((void**)&ylp,  g_yl);
    cudaGetSymbolAddress((void**)&aohp, g_aoh);
    cudaGetSymbolAddress((void**)&aolp, g_aol);
    cudaGetSymbolAddress((void**)&whp,  g_wh);
    cudaGetSymbolAddress((void**)&wlp,  g_wl);

    cudaFuncSetAttribute(gemm_hmma_kernel, cudaFuncAttributeMaxDynamicSharedMemorySize, GEMM_SMEM);

    dwconv_kernel<<<dim3(NPIX / 256, B_ * C_), 256>>>(x, dw);
    convert_w_kernel<<<4096, 256>>>(qw, kw, vw, pw);

    // fused QKV GEMM: M = 1536
    gemm_hmma_kernel<<<dim3(NPIX / 128, 12, B_), 256, GEMM_SMEM>>>(
        whp, wlp, yhp, ylp, qkvp, 1);

    rnorm_kernel<<<3 * B_ * C_, 256>>>();
    scores_part_kernel<<<dim3(8, B_ * HEADS_), 256>>>();
    softmax_kernel<<<B_ * HEADS_, 256>>>();
    attn_apply_kernel<<<dim3(NPIX / 128, B_ * HEADS_), 256>>>();

    // proj GEMM: weight rows [1536, 2048)
    gemm_hmma_kernel<<<dim3(NPIX / 128, 4, B_), 256, GEMM_SMEM>>>(
        whp + 1536 * C_, wlp + 1536 * C_, aohp, aolp, out, 0);
}

// round 5
// speedup vs baseline: 2.8186x; 1.1703x over previous
#include <cuda_runtime.h>
#include <cuda_bf16.h>
#include <math.h>
#include <stdint.h>

#define B_     8
#define C_     512
#define HH     64
#define WW     64
#define NPIX   4096
#define HEADS_ 8
#define HD     64
#define TOFF   (B_ * C_ * NPIX)

// ---------------- scratch ----------------
__device__ __align__(16) __nv_bfloat16 g_yh[TOFF], g_yl[TOFF];       // dwconv out
__device__ __align__(16) __nv_bfloat16 g_qh[TOFF], g_ql[TOFF];
__device__ __align__(16) __nv_bfloat16 g_kh[TOFF], g_kl[TOFF];
__device__ __align__(16) __nv_bfloat16 g_vh[TOFF], g_vl[TOFF];
__device__ __align__(16) __nv_bfloat16 g_aoh[TOFF], g_aol[TOFF];
__device__ __align__(16) __nv_bfloat16 g_wh[4 * C_ * C_], g_wl[4 * C_ * C_];
__device__ __align__(16) __nv_bfloat16 g_ath[B_ * HEADS_ * HD * HD], g_atl[B_ * HEADS_ * HD * HD];
__device__ float g_part[B_ * HEADS_ * 8 * HD * HD];
__device__ float g_sq[3 * B_ * C_];    // sum of squares per (which, b, channel)

// ---------------- PTX helpers (baseline sm_80+) ----------------
__device__ __forceinline__ uint32_t smem_u32(const void* p) {
    uint32_t a;
    asm("{ .reg .u64 t; cvta.to.shared.u64 t, %1; cvt.u32.u64 %0, t; }" : "=r"(a) : "l"(p));
    return a;
}
#define CP16(s, g) asm volatile("cp.async.cg.shared.global [%0], [%1], 16;" :: "r"(s), "l"(g))
#define CP_COMMIT() asm volatile("cp.async.commit_group;" ::: "memory")
#define CP_WAIT1()  asm volatile("cp.async.wait_group 1;" ::: "memory")
#define CP_WAIT0()  asm volatile("cp.async.wait_group 0;" ::: "memory")

#define LDSM_X4(r, a) \
    asm volatile("ldmatrix.sync.aligned.m8n8.x4.shared.b16 {%0,%1,%2,%3}, [%4];" \
        : "=r"((r)[0]), "=r"((r)[1]), "=r"((r)[2]), "=r"((r)[3]) : "r"(a))
#define LDSM_X4T(r, a) \
    asm volatile("ldmatrix.sync.aligned.m8n8.x4.trans.shared.b16 {%0,%1,%2,%3}, [%4];" \
        : "=r"((r)[0]), "=r"((r)[1]), "=r"((r)[2]), "=r"((r)[3]) : "r"(a))
#define MMA16816(d, a, b0, b1) \
    asm volatile("mma.sync.aligned.m16n8k16.row.col.f32.bf16.bf16.f32 " \
        "{%0,%1,%2,%3}, {%4,%5,%6,%7}, {%8,%9}, {%0,%1,%2,%3};" \
        : "+f"((d)[0]), "+f"((d)[1]), "+f"((d)[2]), "+f"((d)[3]) \
        : "r"((a)[0]), "r"((a)[1]), "r"((a)[2]), "r"((a)[3]), "r"(b0), "r"(b1))

__device__ __forceinline__ uint32_t sw128(uint32_t o) { return o ^ ((o >> 3) & 0x70); }

__device__ __forceinline__ void split_f(float v, __nv_bfloat16& hi, __nv_bfloat16& lo) {
    hi = __float2bfloat16_rn(v);
    lo = __float2bfloat16_rn(v - __bfloat162float(hi));
}
__device__ __forceinline__ uint32_t pack2(__nv_bfloat16 a, __nv_bfloat16 b) {
    unsigned short ua = *(unsigned short*)&a, ub = *(unsigned short*)&b;
    return (uint32_t)ua | ((uint32_t)ub << 16);
}
__device__ __forceinline__ float inv_norm(float s) {
    return 1.0f / fmaxf(sqrtf(s), 1e-12f);
}

// ---------------- zero sumsq ----------------
__global__ __launch_bounds__(256) void zero_kernel() {
    for (int i = blockIdx.x * 256 + threadIdx.x; i < 3 * B_ * C_; i += gridDim.x * 256)
        g_sq[i] = 0.f;
}

// ---------------- depthwise 3x3 -> bf16 hi/lo ----------------
__global__ __launch_bounds__(256) void dwconv_kernel(const float* __restrict__ x,
                                                     const float* __restrict__ w) {
    int plane = blockIdx.y;
    int c = plane & (C_ - 1);
    __shared__ float ws[9];
    if (threadIdx.x < 9) ws[threadIdx.x] = w[c * 9 + threadIdx.x];
    __syncthreads();
    int p = blockIdx.x * 256 + threadIdx.x;
    int h = p >> 6, wc = p & 63;
    const float* xp = x + (size_t)plane * NPIX;
    float acc = 0.f;
#pragma unroll
    for (int kh = 0; kh < 3; kh++) {
        int hh = h + kh - 1;
        if (hh < 0 || hh >= HH) continue;
#pragma unroll
        for (int kw = 0; kw < 3; kw++) {
            int wcol = wc + kw - 1;
            if (wcol < 0 || wcol >= WW) continue;
            acc = fmaf(ws[kh * 3 + kw], xp[hh * WW + wcol], acc);
        }
    }
    __nv_bfloat16 hi, lo;
    split_f(acc, hi, lo);
    g_yh[(size_t)plane * NPIX + p] = hi;
    g_yl[(size_t)plane * NPIX + p] = lo;
}

// ---------------- weight conversion ----------------
__global__ __launch_bounds__(256) void convert_w_kernel(const float* __restrict__ qw,
                                                        const float* __restrict__ kw,
                                                        const float* __restrict__ vw,
                                                        const float* __restrict__ pw) {
    int idx = blockIdx.x * 256 + threadIdx.x;
    int m = idx >> 18;
    const float* src = (m == 0) ? qw : (m == 1) ? kw : (m == 2) ? vw : pw;
    float v = src[idx & 262143];
    __nv_bfloat16 hi, lo;
    split_f(v, hi, lo);
    g_wh[idx] = hi;
    g_wl[idx] = lo;
}

// ---------------- bf16 HMMA GEMM, 3x split ----------------
#define A_HI 0
#define A_LO 16384
#define B_HI 32768
#define B_LO 49152
#define STAGE 65536
#define GEMM_SMEM (2 * STAGE)

__global__ __launch_bounds__(256, 1) void gemm_hmma_kernel(const __nv_bfloat16* __restrict__ Wh,
                                                           const __nv_bfloat16* __restrict__ Wl,
                                                           const __nv_bfloat16* __restrict__ Bhg,
                                                           const __nv_bfloat16* __restrict__ Blg,
                                                           float* __restrict__ Cout,
                                                           int qkv_mode) {
    extern __shared__ char smem[];
    uint32_t sb = smem_u32(smem);
    int tid = threadIdx.x;
    int l = tid & 31, wid = tid >> 5;
    int wm = wid & 1, wn = wid >> 1;
    int bn = blockIdx.x * 128;
    int bm = blockIdx.y * 128;
    int bz = blockIdx.z;
    const __nv_bfloat16* Bh = Bhg + (size_t)bz * C_ * NPIX;
    const __nv_bfloat16* Bl = Blg + (size_t)bz * C_ * NPIX;

    auto load_chunk = [&](int chunk, int stg) {
        uint32_t st = sb + stg * STAGE;
        int k0 = chunk * 64;
#pragma unroll
        for (int it = 0; it < 4; it++) {
            int idx = tid + it * 256;
            int ar = idx >> 3;
            int ac = (idx & 7) << 3;
            uint32_t aswo = sw128((uint32_t)(ar * 128 + ac * 2));
            CP16(st + A_HI + aswo, Wh + (size_t)(bm + ar) * C_ + k0 + ac);
            CP16(st + A_LO + aswo, Wl + (size_t)(bm + ar) * C_ + k0 + ac);
            int brr = idx >> 4;
            int bnn = (idx & 15) << 3;
            int s = bnn >> 6, nl = bnn & 63;
            uint32_t bswo = (uint32_t)(s * 8192) + sw128((uint32_t)(brr * 128 + nl * 2));
            CP16(st + B_HI + bswo, Bh + (size_t)(k0 + brr) * NPIX + bn + bnn);
            CP16(st + B_LO + bswo, Bl + (size_t)(k0 + brr) * NPIX + bn + bnn);
        }
    };

    float acc[4][4][4] = {};
    int lr = l & 15;
    int lc = (l >> 4) << 4;

    load_chunk(0, 0); CP_COMMIT();
    load_chunk(1, 1); CP_COMMIT();

    for (int chunk = 0; chunk < 8; chunk++) {
        CP_WAIT1();
        __syncthreads();
        uint32_t st = sb + (chunk & 1) * STAGE;
#pragma unroll
        for (int k16 = 0; k16 < 4; k16++) {
            uint32_t ah[4][4], al[4][4], bh[2][4], bl[2][4];
            int kb = k16 * 32 + lc;
#pragma unroll
            for (int mt = 0; mt < 4; mt++) {
                uint32_t swo = sw128((uint32_t)((wm * 64 + mt * 16 + lr) * 128 + kb));
                LDSM_X4(ah[mt], st + A_HI + swo);
                LDSM_X4(al[mt], st + A_LO + swo);
            }
            uint32_t pb = (uint32_t)((wn >> 1) * 8192);
#pragma unroll
            for (int h = 0; h < 2; h++) {
                uint32_t swo = sw128((uint32_t)((k16 * 16 + lr) * 128 + (wn & 1) * 64 + h * 32 + lc));
                LDSM_X4T(bh[h], st + B_HI + pb + swo);
                LDSM_X4T(bl[h], st + B_LO + pb + swo);
            }
#pragma unroll
            for (int mt = 0; mt < 4; mt++) {
#pragma unroll
                for (int nt = 0; nt < 4; nt++) {
                    int h = nt >> 1, pr = (nt & 1) * 2;
                    MMA16816(acc[mt][nt], ah[mt], bh[h][pr], bh[h][pr + 1]);
                    MMA16816(acc[mt][nt], ah[mt], bl[h][pr], bl[h][pr + 1]);
                    MMA16816(acc[mt][nt], al[mt], bh[h][pr], bh[h][pr + 1]);
                }
            }
        }
        __syncthreads();
        if (chunk + 2 < 8) load_chunk(chunk + 2, chunk & 1);
        CP_COMMIT();
    }

    int l4 = l >> 2, l2 = (l & 3) << 1;
    if (qkv_mode) {
#pragma unroll
        for (int mt = 0; mt < 4; mt++) {
#pragma unroll
            for (int half = 0; half < 2; half++) {
                int row = bm + wm * 64 + mt * 16 + l4 + half * 8;
                int which = row >> 9, ml = row & 511;
                __nv_bfloat16* ph = ((which == 0) ? g_qh : (which == 1) ? g_kh : g_vh)
                                    + ((size_t)bz * C_ + ml) * NPIX;
                __nv_bfloat16* pl = ((which == 0) ? g_ql : (which == 1) ? g_kl : g_vl)
                                    + ((size_t)bz * C_ + ml) * NPIX;
                float ss = 0.f;
#pragma unroll
                for (int nt = 0; nt < 4; nt++) {
                    int col = bn + wn * 32 + nt * 8 + l2;
                    float v0 = acc[mt][nt][half * 2], v1 = acc[mt][nt][half * 2 + 1];
                    ss += v0 * v0 + v1 * v1;
                    __nv_bfloat16 h0, o0, h1, o1;
                    split_f(v0, h0, o0); split_f(v1, h1, o1);
                    *(uint32_t*)(ph + col) = pack2(h0, h1);
                    *(uint32_t*)(pl + col) = pack2(o0, o1);
                }
                ss += __shfl_xor_sync(0xffffffffu, ss, 1);
                ss += __shfl_xor_sync(0xffffffffu, ss, 2);
                if ((l & 3) == 0)
                    atomicAdd(&g_sq[which * (B_ * C_) + bz * C_ + ml], ss);
            }
        }
    } else {
#pragma unroll
        for (int mt = 0; mt < 4; mt++) {
#pragma unroll
            for (int half = 0; half < 2; half++) {
                int row = bm + wm * 64 + mt * 16 + l4 + half * 8;
                float* base = Cout + ((size_t)bz * C_ + row) * NPIX;
#pragma unroll
                for (int nt = 0; nt < 4; nt++) {
                    int col = bn + wn * 32 + nt * 8 + l2;
                    *(float2*)(base + col) =
                        make_float2(acc[mt][nt][half * 2], acc[mt][nt][half * 2 + 1]);
                }
            }
        }
    }
}

// ---------------- scores: HMMA, split-K partials ----------------
// CTA: (sp, bh). Tiles 64 rows x 64 px (128B rows), q/k hi/lo, double buffered.
#define SC_QH 0
#define SC_QL 8192
#define SC_KH 16384
#define SC_KL 24576
#define SC_STAGE 32768
#define SC_SMEM (2 * SC_STAGE)

__global__ __launch_bounds__(256, 1) void scores_kernel() {
    extern __shared__ char smem[];
    uint32_t sb = smem_u32(smem);
    int sp = blockIdx.x, bh = blockIdx.y;
    int b = bh >> 3, hg = bh & 7;
    int tid = threadIdx.x, l = tid & 31, wid = tid >> 5;
    int wm = wid & 1, wn = wid >> 1;
    const __nv_bfloat16* qh = g_qh + ((size_t)b * C_ + hg * HD) * NPIX;
    const __nv_bfloat16* ql = g_ql + ((size_t)b * C_ + hg * HD) * NPIX;
    const __nv_bfloat16* kh = g_kh + ((size_t)b * C_ + hg * HD) * NPIX;
    const __nv_bfloat16* kl = g_kl + ((size_t)b * C_ + hg * HD) * NPIX;
    int px0 = sp * 512;

    auto load_chunk = [&](int chunk, int stg) {
        uint32_t st = sb + stg * SC_STAGE;
        int k0 = px0 + chunk * 64;
#pragma unroll
        for (int it = 0; it < 2; it++) {
            int idx = tid + it * 256;      // 0..511
            int r = idx >> 3;
            int c8 = idx & 7;
            uint32_t swo = sw128((uint32_t)(r * 128 + c8 * 16));
            size_t go = (size_t)r * NPIX + k0 + c8 * 8;
            CP16(st + SC_QH + swo, qh + go);
            CP16(st + SC_QL + swo, ql + go);
            CP16(st + SC_KH + swo, kh + go);
            CP16(st + SC_KL + swo, kl + go);
        }
    };

    float acc[2][2][4] = {};
    int lr = l & 15, lc = (l >> 4) << 4;
    int bn_row = wn * 16 + (l & 7) + ((l >> 4) << 3);
    int bn_kb = ((l >> 3) & 1) * 16;

    load_chunk(0, 0); CP_COMMIT();
    load_chunk(1, 1); CP_COMMIT();

    for (int chunk = 0; chunk < 8; chunk++) {
        CP_WAIT1();
        __syncthreads();
        uint32_t st = sb + (chunk & 1) * SC_STAGE;
#pragma unroll
        for (int k16 = 0; k16 < 4; k16++) {
            uint32_t ah[2][4], al[2][4], bhf[4], blf[4];
#pragma unroll
            for (int mt = 0; mt < 2; mt++) {
                uint32_t swo = sw128((uint32_t)((wm * 32 + mt * 16 + lr) * 128 + k16 * 32 + lc));
                LDSM_X4(ah[mt], st + SC_QH + swo);
                LDSM_X4(al[mt], st + SC_QL + swo);
            }
            uint32_t swb = sw128((uint32_t)(bn_row * 128 + k16 * 32 + bn_kb));
            LDSM_X4(bhf, st + SC_KH + swb);
            LDSM_X4(blf, st + SC_KL + swb);
#pragma unroll
            for (int mt = 0; mt < 2; mt++)
#pragma unroll
                for (int nt = 0; nt < 2; nt++) {
                    MMA16816(acc[mt][nt], ah[mt], bhf[nt * 2], bhf[nt * 2 + 1]);
                    MMA16816(acc[mt][nt], ah[mt], blf[nt * 2], blf[nt * 2 + 1]);
                    MMA16816(acc[mt][nt], al[mt], bhf[nt * 2], bhf[nt * 2 + 1]);
                }
        }
        __syncthreads();
        if (chunk + 2 < 8) load_chunk(chunk + 2, chunk & 1);
        CP_COMMIT();
    }

    float* op = g_part + ((size_t)bh * 8 + sp) * 4096;
    int l4 = l >> 2, l2 = (l & 3) << 1;
#pragma unroll
    for (int mt = 0; mt < 2; mt++)
#pragma unroll
        for (int half = 0; half < 2; half++) {
            int row = wm * 32 + mt * 16 + l4 + half * 8;
#pragma unroll
            for (int nt = 0; nt < 2; nt++) {
                int col = wn * 16 + nt * 8 + l2;
                *(float2*)(op + row * 64 + col) =
                    make_float2(acc[mt][nt][half * 2], acc[mt][nt][half * 2 + 1]);
            }
        }
}

// ---------------- reduce + softmax, fold norms, -> attn bf16 hi/lo ----------------
__global__ __launch_bounds__(256) void softmax_kernel() {
    int bh = blockIdx.x;
    int b = bh >> 3, hg = bh & 7;
    int cb = b * C_ + hg * HD;
    __shared__ float Ss[64][64];
    __shared__ float rv_s[64];
    int tid = threadIdx.x;
    const float scale = 0.125f;
    if (tid < 64) rv_s[tid] = inv_norm(g_sq[2 * B_ * C_ + cb + tid]);
    for (int i = tid; i < 4096; i += 256) {
        float s = 0.f;
#pragma unroll
        for (int p = 0; p < 8; p++) s += g_part[((size_t)bh * 8 + p) * 4096 + i];
        int r = i >> 6, c = i & 63;
        Ss[r][c] = s * inv_norm(g_sq[cb + r]) * scale * inv_norm(g_sq[B_ * C_ + cb + c]);
    }
    __syncthreads();
    int warp = tid >> 5, lane = tid & 31;
#pragma unroll
    for (int rr = 0; rr < 8; rr++) {
        int r = warp * 8 + rr;
        float v0 = Ss[r][lane], v1 = Ss[r][lane + 32];
        float m = fmaxf(v0, v1);
#pragma unroll
        for (int off = 16; off; off >>= 1) m = fmaxf(m, __shfl_xor_sync(0xffffffffu, m, off));
        float e0 = __expf(v0 - m), e1 = __expf(v1 - m);
        float s = e0 + e1;
#pragma unroll
        for (int off = 16; off; off >>= 1) s += __shfl_xor_sync(0xffffffffu, s, off);
        float inv = 1.0f / s;
        float a0 = e0 * inv * rv_s[lane];
        float a1 = e1 * inv * rv_s[lane + 32];
        __nv_bfloat16 h, o;
        size_t base = (size_t)bh * 4096 + r * 64;
        split_f(a0, h, o);
        g_ath[base + lane] = h;      g_atl[base + lane] = o;
        split_f(a1, h, o);
        g_ath[base + lane + 32] = h; g_atl[base + lane + 32] = o;
    }
}

// ---------------- apply: HMMA mini-GEMM out = attn @ v -> ao bf16 hi/lo ----------------
#define AP_AH 0
#define AP_AL 8192
#define AP_VH 16384
#define AP_VL 32768
#define AP_SMEM 49152

__global__ __launch_bounds__(256, 1) void apply_kernel() {
    extern __shared__ char smem[];
    uint32_t sb = smem_u32(smem);
    int ntile = blockIdx.x;    // 0..31
    int bh = blockIdx.y;
    int b = bh >> 3, hg = bh & 7;
    int tid = threadIdx.x, l = tid & 31, wid = tid >> 5;
    int wm = wid & 1, wn = wid >> 1;

    // attn tile 64x64 (128B rows)
#pragma unroll
    for (int it = 0; it < 2; it++) {
        int idx = tid + it * 256;
        int r = idx >> 3, c8 = idx & 7;
        uint32_t swo = sw128((uint32_t)(r * 128 + c8 * 16));
        size_t go = (size_t)bh * 4096 + r * 64 + c8 * 8;
        CP16(sb + AP_AH + swo, g_ath + go);
        CP16(sb + AP_AL + swo, g_atl + go);
    }
    // v tile 64 rows(e) x 128 n, two 64-col subtiles
    const __nv_bfloat16* vh = g_vh + ((size_t)b * C_ + hg * HD) * NPIX + ntile * 128;
    const __nv_bfloat16* vl = g_vl + ((size_t)b * C_ + hg * HD) * NPIX + ntile * 128;
#pragma unroll
    for (int it = 0; it < 4; it++) {
        int idx = tid + it * 256;
        int r = idx >> 4;
        int n8 = idx & 15;
        int s = n8 >> 3, nl = n8 & 7;
        uint32_t swo = (uint32_t)(s * 8192) + sw128((uint32_t)(r * 128 + nl * 16));
        CP16(sb + AP_VH + swo, vh + (size_t)r * NPIX + n8 * 8);
        CP16(sb + AP_VL + swo, vl + (size_t)r * NPIX + n8 * 8);
    }
    CP_COMMIT();
    CP_WAIT0();
    __syncthreads();

    float acc[2][4][4] = {};
    int lr = l & 15, lc = (l >> 4) << 4;
#pragma unroll
    for (int k16 = 0; k16 < 4; k16++) {
        uint32_t ah[2][4], al[2][4], bhf[2][4], blf[2][4];
#pragma unroll
        for (int mt = 0; mt < 2; mt++) {
            uint32_t swo = sw128((uint32_t)((wm * 32 + mt * 16 + lr) * 128 + k16 * 32 + lc));
            LDSM_X4(ah[mt], sb + AP_AH + swo);
            LDSM_X4(al[mt], sb + AP_AL + swo);
        }
        uint32_t pb = (uint32_t)((wn >> 1) * 8192);
#pragma unroll
        for (int h = 0; h < 2; h++) {
            uint32_t swo = sw128((uint32_t)((k16 * 16 + lr) * 128 + (wn & 1) * 64 + h * 32 + lc));
            LDSM_X4T(bhf[h], sb + AP_VH + pb + swo);
            LDSM_X4T(blf[h], sb + AP_VL + pb + swo);
        }
#pragma unroll
        for (int mt = 0; mt < 2; mt++)
#pragma unroll
            for (int nt = 0; nt < 4; nt++) {
                int h = nt >> 1, pr = (nt & 1) * 2;
                MMA16816(acc[mt][nt], ah[mt], bhf[h][pr], bhf[h][pr + 1]);
                MMA16816(acc[mt][nt], ah[mt], blf[h][pr], blf[h][pr + 1]);
                MMA16816(acc[mt][nt], al[mt], bhf[h][pr], bhf[h][pr + 1]);
            }
    }

    int l4 = l >> 2, l2 = (l & 3) << 1;
#pragma unroll
    for (int mt = 0; mt < 2; mt++)
#pragma unroll
        for (int half = 0; half < 2; half++) {
            int row = wm * 32 + mt * 16 + l4 + half * 8;
            __nv_bfloat16* ph = g_aoh + ((size_t)b * C_ + hg * HD + row) * NPIX + ntile * 128;
            __nv_bfloat16* pl = g_aol + ((size_t)b * C_ + hg * HD + row) * NPIX + ntile * 128;
#pragma unroll
            for (int nt = 0; nt < 4; nt++) {
                int col = wn * 32 + nt * 8 + l2;
                float v0 = acc[mt][nt][half * 2], v1 = acc[mt][nt][half * 2 + 1];
                __nv_bfloat16 h0, o0, h1, o1;
                split_f(v0, h0, o0); split_f(v1, h1, o1);
                *(uint32_t*)(ph + col) = pack2(h0, h1);
                *(uint32_t*)(pl + col) = pack2(o0, o1);
            }
        }
}

// ---------------- launch ----------------
extern "C" void kernel_launch(void* const* d_in, const int* in_sizes, int n_in,
                              void* d_out, int out_size) {
    const float* x  = (const float*)d_in[0];
    const float* dw = (const float*)d_in[1];
    const float* qw = (const float*)d_in[2];
    const float* kw = (const float*)d_in[3];
    const float* vw = (const float*)d_in[4];
    const float* pw = (const float*)d_in[5];
    float* out = (float*)d_out;

    __nv_bfloat16 *yhp, *ylp, *aohp, *aolp, *whp, *wlp;
    cudaGetSymbolAddress((void**)&yhp,  g_yh);
    cudaGetSymbolAddress((void**)&ylp,  g_yl);
    cudaGetSymbolAddress((void**)&aohp, g_aoh);
    cudaGetSymbolAddress((void**)&aolp, g_aol);
    cudaGetSymbolAddress((void**)&whp,  g_wh);
    cudaGetSymbolAddress((void**)&wlp,  g_wl);

    cudaFuncSetAttribute(gemm_hmma_kernel, cudaFuncAttributeMaxDynamicSharedMemorySize, GEMM_SMEM);
    cudaFuncSetAttribute(scores_kernel, cudaFuncAttributeMaxDynamicSharedMemorySize, SC_SMEM);
    cudaFuncSetAttribute(apply_kernel, cudaFuncAttributeMaxDynamicSharedMemorySize, AP_SMEM);

    zero_kernel<<<16, 256>>>();                                    // 1
    dwconv_kernel<<<dim3(NPIX / 256, B_ * C_), 256>>>(x, dw);      // 2
    convert_w_kernel<<<4096, 256>>>(qw, kw, vw, pw);               // 3
    // fused QKV GEMM, M=1536 (profiled slot)
    gemm_hmma_kernel<<<dim3(NPIX / 128, 12, B_), 256, GEMM_SMEM>>>(// 4
        whp, wlp, yhp, ylp, nullptr, 1);
    scores_kernel<<<dim3(8, B_ * HEADS_), 256, SC_SMEM>>>();       // 5
    softmax_kernel<<<B_ * HEADS_, 256>>>();                        // 6
    apply_kernel<<<dim3(NPIX / 128, B_ * HEADS_), 256, AP_SMEM>>>();// 7
    // proj GEMM
    gemm_hmma_kernel<<<dim3(NPIX / 128, 4, B_), 256, GEMM_SMEM>>>( // 8
        whp + 1536 * C_, wlp + 1536 * C_, aohp, aolp, out, 0);
}

// round 6
// speedup vs baseline: 3.0467x; 1.0809x over previous
#include <cuda_runtime.h>
#include <cuda_bf16.h>
#include <math.h>
#include <stdint.h>

#define B_     8
#define C_     512
#define HH     64
#define WW     64
#define NPIX   4096
#define HEADS_ 8
#define HD     64
#define TOFF   (B_ * C_ * NPIX)

// ---------------- scratch ----------------
__device__ __align__(16) __nv_bfloat16 g_yh[TOFF], g_yl[TOFF];
__device__ __align__(16) __nv_bfloat16 g_qh[TOFF], g_ql[TOFF];
__device__ __align__(16) __nv_bfloat16 g_kh[TOFF], g_kl[TOFF];
__device__ __align__(16) __nv_bfloat16 g_vh[TOFF], g_vl[TOFF];
__device__ __align__(16) __nv_bfloat16 g_aoh[TOFF], g_aol[TOFF];
__device__ __align__(16) __nv_bfloat16 g_wh[4 * C_ * C_], g_wl[4 * C_ * C_];
__device__ __align__(16) __nv_bfloat16 g_ath[B_ * HEADS_ * HD * HD], g_atl[B_ * HEADS_ * HD * HD];
__device__ float g_part[B_ * HEADS_ * 8 * HD * HD];
__device__ float g_sq[3 * B_ * C_];

// ---------------- PTX helpers (baseline sm_80+) ----------------
__device__ __forceinline__ uint32_t smem_u32(const void* p) {
    uint32_t a;
    asm("{ .reg .u64 t; cvta.to.shared.u64 t, %1; cvt.u32.u64 %0, t; }" : "=r"(a) : "l"(p));
    return a;
}
#define CP16(s, g) asm volatile("cp.async.cg.shared.global [%0], [%1], 16;" :: "r"(s), "l"(g))
#define CP_COMMIT() asm volatile("cp.async.commit_group;" ::: "memory")
#define CP_WAIT1()  asm volatile("cp.async.wait_group 1;" ::: "memory")
#define CP_WAIT0()  asm volatile("cp.async.wait_group 0;" ::: "memory")

#define LDSM_X4(r, a) \
    asm volatile("ldmatrix.sync.aligned.m8n8.x4.shared.b16 {%0,%1,%2,%3}, [%4];" \
        : "=r"((r)[0]), "=r"((r)[1]), "=r"((r)[2]), "=r"((r)[3]) : "r"(a))
#define LDSM_X4T(r, a) \
    asm volatile("ldmatrix.sync.aligned.m8n8.x4.trans.shared.b16 {%0,%1,%2,%3}, [%4];" \
        : "=r"((r)[0]), "=r"((r)[1]), "=r"((r)[2]), "=r"((r)[3]) : "r"(a))
#define MMA16816(d, a, b0, b1) \
    asm volatile("mma.sync.aligned.m16n8k16.row.col.f32.bf16.bf16.f32 " \
        "{%0,%1,%2,%3}, {%4,%5,%6,%7}, {%8,%9}, {%0,%1,%2,%3};" \
        : "+f"((d)[0]), "+f"((d)[1]), "+f"((d)[2]), "+f"((d)[3]) \
        : "r"((a)[0]), "r"((a)[1]), "r"((a)[2]), "r"((a)[3]), "r"(b0), "r"(b1))

__device__ __forceinline__ uint32_t sw128(uint32_t o) { return o ^ ((o >> 3) & 0x70); }

__device__ __forceinline__ void split_f(float v, __nv_bfloat16& hi, __nv_bfloat16& lo) {
    hi = __float2bfloat16_rn(v);
    lo = __float2bfloat16_rn(v - __bfloat162float(hi));
}
__device__ __forceinline__ uint32_t pack2(__nv_bfloat16 a, __nv_bfloat16 b) {
    unsigned short ua = *(unsigned short*)&a, ub = *(unsigned short*)&b;
    return (uint32_t)ua | ((uint32_t)ub << 16);
}
__device__ __forceinline__ float inv_norm(float s) {
    return 1.0f / fmaxf(sqrtf(s), 1e-12f);
}

// ---------------- zero sumsq ----------------
__global__ __launch_bounds__(256) void zero_kernel() {
    for (int i = blockIdx.x * 256 + threadIdx.x; i < 3 * B_ * C_; i += gridDim.x * 256)
        g_sq[i] = 0.f;
}

// ---------------- depthwise 3x3 -> bf16 hi/lo ----------------
__global__ __launch_bounds__(256) void dwconv_kernel(const float* __restrict__ x,
                                                     const float* __restrict__ w) {
    int plane = blockIdx.y;
    int c = plane & (C_ - 1);
    __shared__ float ws[9];
    if (threadIdx.x < 9) ws[threadIdx.x] = w[c * 9 + threadIdx.x];
    __syncthreads();
    int p = blockIdx.x * 256 + threadIdx.x;
    int h = p >> 6, wc = p & 63;
    const float* xp = x + (size_t)plane * NPIX;
    float acc = 0.f;
#pragma unroll
    for (int kh = 0; kh < 3; kh++) {
        int hh = h + kh - 1;
        if (hh < 0 || hh >= HH) continue;
#pragma unroll
        for (int kw = 0; kw < 3; kw++) {
            int wcol = wc + kw - 1;
            if (wcol < 0 || wcol >= WW) continue;
            acc = fmaf(ws[kh * 3 + kw], xp[hh * WW + wcol], acc);
        }
    }
    __nv_bfloat16 hi, lo;
    split_f(acc, hi, lo);
    g_yh[(size_t)plane * NPIX + p] = hi;
    g_yl[(size_t)plane * NPIX + p] = lo;
}

// ---------------- weight conversion ----------------
__global__ __launch_bounds__(256) void convert_w_kernel(const float* __restrict__ qw,
                                                        const float* __restrict__ kw,
                                                        const float* __restrict__ vw,
                                                        const float* __restrict__ pw) {
    int idx = blockIdx.x * 256 + threadIdx.x;
    int m = idx >> 18;
    const float* src = (m == 0) ? qw : (m == 1) ? kw : (m == 2) ? vw : pw;
    float v = src[idx & 262143];
    __nv_bfloat16 hi, lo;
    split_f(v, hi, lo);
    g_wh[idx] = hi;
    g_wl[idx] = lo;
}

// ---------------- bf16 HMMA GEMM, 3x split, M-tile 64 (2 CTAs/SM) ----------------
#define A_HI 0
#define A_LO 8192
#define B_HI 16384
#define B_LO 32768
#define STAGE 49152
#define GEMM_SMEM (2 * STAGE)

__global__ __launch_bounds__(256, 2) void gemm_hmma_kernel(const __nv_bfloat16* __restrict__ Wh,
                                                           const __nv_bfloat16* __restrict__ Wl,
                                                           const __nv_bfloat16* __restrict__ Bhg,
                                                           const __nv_bfloat16* __restrict__ Blg,
                                                           float* __restrict__ Cout,
                                                           int qkv_mode) {
    extern __shared__ char smem[];
    uint32_t sb = smem_u32(smem);
    int tid = threadIdx.x;
    int l = tid & 31, wid = tid >> 5;
    int wm = wid & 1, wn = wid >> 1;        // warp tile: 32 rows x 32 cols
    int bn = blockIdx.x * 128;
    int bm = blockIdx.y * 64;
    int bz = blockIdx.z;
    const __nv_bfloat16* Bh = Bhg + (size_t)bz * C_ * NPIX;
    const __nv_bfloat16* Bl = Blg + (size_t)bz * C_ * NPIX;

    // A tile: 64 rows x 64 K (128B rows, SW128). B tile: 64 K-rows x 128 N (two 64-col subtiles).
    auto load_chunk = [&](int chunk, int stg) {
        uint32_t st = sb + stg * STAGE;
        int k0 = chunk * 64;
#pragma unroll
        for (int it = 0; it < 2; it++) {
            int idx = tid + it * 256;              // 0..511
            int ar = idx >> 3;                     // 0..63
            int ac = (idx & 7) << 3;
            uint32_t aswo = sw128((uint32_t)(ar * 128 + ac * 2));
            CP16(st + A_HI + aswo, Wh + (size_t)(bm + ar) * C_ + k0 + ac);
            CP16(st + A_LO + aswo, Wl + (size_t)(bm + ar) * C_ + k0 + ac);
        }
#pragma unroll
        for (int it = 0; it < 4; it++) {
            int idx = tid + it * 256;              // 0..1023
            int brr = idx >> 4;                    // 0..63
            int bnn = (idx & 15) << 3;             // 0..120
            int s = bnn >> 6, nl = bnn & 63;
            uint32_t bswo = (uint32_t)(s * 8192) + sw128((uint32_t)(brr * 128 + nl * 2));
            CP16(st + B_HI + bswo, Bh + (size_t)(k0 + brr) * NPIX + bn + bnn);
            CP16(st + B_LO + bswo, Bl + (size_t)(k0 + brr) * NPIX + bn + bnn);
        }
    };

    float acc[2][4][4] = {};
    int lr = l & 15;
    int lc = (l >> 4) << 4;

    load_chunk(0, 0); CP_COMMIT();
    load_chunk(1, 1); CP_COMMIT();

    for (int chunk = 0; chunk < 8; chunk++) {
        CP_WAIT1();
        __syncthreads();
        uint32_t st = sb + (chunk & 1) * STAGE;
#pragma unroll
        for (int k16 = 0; k16 < 4; k16++) {
            uint32_t ah[2][4], al[2][4], bh[2][4], bl[2][4];
            int kb = k16 * 32 + lc;
#pragma unroll
            for (int mt = 0; mt < 2; mt++) {
                uint32_t swo = sw128((uint32_t)((wm * 32 + mt * 16 + lr) * 128 + kb));
                LDSM_X4(ah[mt], st + A_HI + swo);
                LDSM_X4(al[mt], st + A_LO + swo);
            }
            uint32_t pb = (uint32_t)((wn >> 1) * 8192);
#pragma unroll
            for (int h = 0; h < 2; h++) {
                uint32_t swo = sw128((uint32_t)((k16 * 16 + lr) * 128 + (wn & 1) * 64 + h * 32 + lc));
                LDSM_X4T(bh[h], st + B_HI + pb + swo);
                LDSM_X4T(bl[h], st + B_LO + pb + swo);
            }
#pragma unroll
            for (int mt = 0; mt < 2; mt++) {
#pragma unroll
                for (int nt = 0; nt < 4; nt++) {
                    int h = nt >> 1, pr = (nt & 1) * 2;
                    MMA16816(acc[mt][nt], ah[mt], bh[h][pr], bh[h][pr + 1]);
                    MMA16816(acc[mt][nt], ah[mt], bl[h][pr], bl[h][pr + 1]);
                    MMA16816(acc[mt][nt], al[mt], bh[h][pr], bh[h][pr + 1]);
                }
            }
        }
        __syncthreads();
        if (chunk + 2 < 8) load_chunk(chunk + 2, chunk & 1);
        CP_COMMIT();
    }

    int l4 = l >> 2, l2 = (l & 3) << 1;
    if (qkv_mode) {
#pragma unroll
        for (int mt = 0; mt < 2; mt++) {
#pragma unroll
            for (int half = 0; half < 2; half++) {
                int row = bm + wm * 32 + mt * 16 + l4 + half * 8;
                int which = row >> 9, ml = row & 511;
                __nv_bfloat16* ph = ((which == 0) ? g_qh : (which == 1) ? g_kh : g_vh)
                                    + ((size_t)bz * C_ + ml) * NPIX;
                __nv_bfloat16* pl = ((which == 0) ? g_ql : (which == 1) ? g_kl : g_vl)
                                    + ((size_t)bz * C_ + ml) * NPIX;
                float ss = 0.f;
#pragma unroll
                for (int nt = 0; nt < 4; nt++) {
                    int col = bn + wn * 32 + nt * 8 + l2;
                    float v0 = acc[mt][nt][half * 2], v1 = acc[mt][nt][half * 2 + 1];
                    ss += v0 * v0 + v1 * v1;
                    __nv_bfloat16 h0, o0, h1, o1;
                    split_f(v0, h0, o0); split_f(v1, h1, o1);
                    *(uint32_t*)(ph + col) = pack2(h0, h1);
                    *(uint32_t*)(pl + col) = pack2(o0, o1);
                }
                ss += __shfl_xor_sync(0xffffffffu, ss, 1);
                ss += __shfl_xor_sync(0xffffffffu, ss, 2);
                if ((l & 3) == 0)
                    atomicAdd(&g_sq[which * (B_ * C_) + bz * C_ + ml], ss);
            }
        }
    } else {
#pragma unroll
        for (int mt = 0; mt < 2; mt++) {
#pragma unroll
            for (int half = 0; half < 2; half++) {
                int row = bm + wm * 32 + mt * 16 + l4 + half * 8;
                float* base = Cout + ((size_t)bz * C_ + row) * NPIX;
#pragma unroll
                for (int nt = 0; nt < 4; nt++) {
                    int col = bn + wn * 32 + nt * 8 + l2;
                    *(float2*)(base + col) =
                        make_float2(acc[mt][nt][half * 2], acc[mt][nt][half * 2 + 1]);
                }
            }
        }
    }
}

// ---------------- scores: HMMA, split-K partials ----------------
#define SC_QH 0
#define SC_QL 8192
#define SC_KH 16384
#define SC_KL 24576
#define SC_STAGE 32768
#define SC_SMEM (2 * SC_STAGE)

__global__ __launch_bounds__(256) void scores_kernel() {
    extern __shared__ char smem[];
    uint32_t sb = smem_u32(smem);
    int sp = blockIdx.x, bh = blockIdx.y;
    int b = bh >> 3, hg = bh & 7;
    int tid = threadIdx.x, l = tid & 31, wid = tid >> 5;
    int wm = wid & 1, wn = wid >> 1;
    const __nv_bfloat16* qh = g_qh + ((size_t)b * C_ + hg * HD) * NPIX;
    const __nv_bfloat16* ql = g_ql + ((size_t)b * C_ + hg * HD) * NPIX;
    const __nv_bfloat16* kh = g_kh + ((size_t)b * C_ + hg * HD) * NPIX;
    const __nv_bfloat16* kl = g_kl + ((size_t)b * C_ + hg * HD) * NPIX;
    int px0 = sp * 512;

    auto load_chunk = [&](int chunk, int stg) {
        uint32_t st = sb + stg * SC_STAGE;
        int k0 = px0 + chunk * 64;
#pragma unroll
        for (int it = 0; it < 2; it++) {
            int idx = tid + it * 256;
            int r = idx >> 3;
            int c8 = idx & 7;
            uint32_t swo = sw128((uint32_t)(r * 128 + c8 * 16));
            size_t go = (size_t)r * NPIX + k0 + c8 * 8;
            CP16(st + SC_QH + swo, qh + go);
            CP16(st + SC_QL + swo, ql + go);
            CP16(st + SC_KH + swo, kh + go);
            CP16(st + SC_KL + swo, kl + go);
        }
    };

    float acc[2][2][4] = {};
    int lr = l & 15, lc = (l >> 4) << 4;
    int bn_row = wn * 16 + (l & 7) + ((l >> 4) << 3);
    int bn_kb = ((l >> 3) & 1) * 16;

    load_chunk(0, 0); CP_COMMIT();
    load_chunk(1, 1); CP_COMMIT();

    for (int chunk = 0; chunk < 8; chunk++) {
        CP_WAIT1();
        __syncthreads();
        uint32_t st = sb + (chunk & 1) * SC_STAGE;
#pragma unroll
        for (int k16 = 0; k16 < 4; k16++) {
            uint32_t ah[2][4], al[2][4], bhf[4], blf[4];
#pragma unroll
            for (int mt = 0; mt < 2; mt++) {
                uint32_t swo = sw128((uint32_t)((wm * 32 + mt * 16 + lr) * 128 + k16 * 32 + lc));
                LDSM_X4(ah[mt], st + SC_QH + swo);
                LDSM_X4(al[mt], st + SC_QL + swo);
            }
            uint32_t swb = sw128((uint32_t)(bn_row * 128 + k16 * 32 + bn_kb));
            LDSM_X4(bhf, st + SC_KH + swb);
            LDSM_X4(blf, st + SC_KL + swb);
#pragma unroll
            for (int mt = 0; mt < 2; mt++)
#pragma unroll
                for (int nt = 0; nt < 2; nt++) {
                    MMA16816(acc[mt][nt], ah[mt], bhf[nt * 2], bhf[nt * 2 + 1]);
                    MMA16816(acc[mt][nt], ah[mt], blf[nt * 2], blf[nt * 2 + 1]);
                    MMA16816(acc[mt][nt], al[mt], bhf[nt * 2], bhf[nt * 2 + 1]);
                }
        }
        __syncthreads();
        if (chunk + 2 < 8) load_chunk(chunk + 2, chunk & 1);
        CP_COMMIT();
    }

    float* op = g_part + ((size_t)bh * 8 + sp) * 4096;
    int l4 = l >> 2, l2 = (l & 3) << 1;
#pragma unroll
    for (int mt = 0; mt < 2; mt++)
#pragma unroll
        for (int half = 0; half < 2; half++) {
            int row = wm * 32 + mt * 16 + l4 + half * 8;
#pragma unroll
            for (int nt = 0; nt < 2; nt++) {
                int col = wn * 16 + nt * 8 + l2;
                *(float2*)(op + row * 64 + col) =
                    make_float2(acc[mt][nt][half * 2], acc[mt][nt][half * 2 + 1]);
            }
        }
}

// ---------------- reduce + softmax, fold norms, -> attn bf16 hi/lo ----------------
__global__ __launch_bounds__(256) void softmax_kernel() {
    int bh = blockIdx.x;
    int b = bh >> 3, hg = bh & 7;
    int cb = b * C_ + hg * HD;
    __shared__ float Ss[64][64];
    __shared__ float rv_s[64];
    int tid = threadIdx.x;
    const float scale = 0.125f;
    if (tid < 64) rv_s[tid] = inv_norm(g_sq[2 * B_ * C_ + cb + tid]);
    for (int i = tid; i < 4096; i += 256) {
        float s = 0.f;
#pragma unroll
        for (int p = 0; p < 8; p++) s += g_part[((size_t)bh * 8 + p) * 4096 + i];
        int r = i >> 6, c = i & 63;
        Ss[r][c] = s * inv_norm(g_sq[cb + r]) * scale * inv_norm(g_sq[B_ * C_ + cb + c]);
    }
    __syncthreads();
    int warp = tid >> 5, lane = tid & 31;
#pragma unroll
    for (int rr = 0; rr < 8; rr++) {
        int r = warp * 8 + rr;
        float v0 = Ss[r][lane], v1 = Ss[r][lane + 32];
        float m = fmaxf(v0, v1);
#pragma unroll
        for (int off = 16; off; off >>= 1) m = fmaxf(m, __shfl_xor_sync(0xffffffffu, m, off));
        float e0 = __expf(v0 - m), e1 = __expf(v1 - m);
        float s = e0 + e1;
#pragma unroll
        for (int off = 16; off; off >>= 1) s += __shfl_xor_sync(0xffffffffu, s, off);
        float inv = 1.0f / s;
        float a0 = e0 * inv * rv_s[lane];
        float a1 = e1 * inv * rv_s[lane + 32];
        __nv_bfloat16 h, o;
        size_t base = (size_t)bh * 4096 + r * 64;
        split_f(a0, h, o);
        g_ath[base + lane] = h;      g_atl[base + lane] = o;
        split_f(a1, h, o);
        g_ath[base + lane + 32] = h; g_atl[base + lane + 32] = o;
    }
}

// ---------------- apply: HMMA mini-GEMM out = attn @ v -> ao bf16 hi/lo ----------------
#define AP_AH 0
#define AP_AL 8192
#define AP_VH 16384
#define AP_VL 32768
#define AP_SMEM 49152

__global__ __launch_bounds__(256) void apply_kernel() {
    extern __shared__ char smem[];
    uint32_t sb = smem_u32(smem);
    int ntile = blockIdx.x;
    int bh = blockIdx.y;
    int b = bh >> 3, hg = bh & 7;
    int tid = threadIdx.x, l = tid & 31, wid = tid >> 5;
    int wm = wid & 1, wn = wid >> 1;

#pragma unroll
    for (int it = 0; it < 2; it++) {
        int idx = tid + it * 256;
        int r = idx >> 3, c8 = idx & 7;
        uint32_t swo = sw128((uint32_t)(r * 128 + c8 * 16));
        size_t go = (size_t)bh * 4096 + r * 64 + c8 * 8;
        CP16(sb + AP_AH + swo, g_ath + go);
        CP16(sb + AP_AL + swo, g_atl + go);
    }
    const __nv_bfloat16* vh = g_vh + ((size_t)b * C_ + hg * HD) * NPIX + ntile * 128;
    const __nv_bfloat16* vl = g_vl + ((size_t)b * C_ + hg * HD) * NPIX + ntile * 128;
#pragma unroll
    for (int it = 0; it < 4; it++) {
        int idx = tid + it * 256;
        int r = idx >> 4;
        int n8 = idx & 15;
        int s = n8 >> 3, nl = n8 & 7;
        uint32_t swo = (uint32_t)(s * 8192) + sw128((uint32_t)(r * 128 + nl * 16));
        CP16(sb + AP_VH + swo, vh + (size_t)r * NPIX + n8 * 8);
        CP16(sb + AP_VL + swo, vl + (size_t)r * NPIX + n8 * 8);
    }
    CP_COMMIT();
    CP_WAIT0();
    __syncthreads();

    float acc[2][4][4] = {};
    int lr = l & 15, lc = (l >> 4) << 4;
#pragma unroll
    for (int k16 = 0; k16 < 4; k16++) {
        uint32_t ah[2][4], al[2][4], bhf[2][4], blf[2][4];
#pragma unroll
        for (int mt = 0; mt < 2; mt++) {
            uint32_t swo = sw128((uint32_t)((wm * 32 + mt * 16 + lr) * 128 + k16 * 32 + lc));
            LDSM_X4(ah[mt], sb + AP_AH + swo);
            LDSM_X4(al[mt], sb + AP_AL + swo);
        }
        uint32_t pb = (uint32_t)((wn >> 1) * 8192);
#pragma unroll
        for (int h = 0; h < 2; h++) {
            uint32_t swo = sw128((uint32_t)((k16 * 16 + lr) * 128 + (wn & 1) * 64 + h * 32 + lc));
            LDSM_X4T(bhf[h], sb + AP_VH + pb + swo);
            LDSM_X4T(blf[h], sb + AP_VL + pb + swo);
        }
#pragma unroll
        for (int mt = 0; mt < 2; mt++)
#pragma unroll
            for (int nt = 0; nt < 4; nt++) {
                int h = nt >> 1, pr = (nt & 1) * 2;
                MMA16816(acc[mt][nt], ah[mt], bhf[h][pr], bhf[h][pr + 1]);
                MMA16816(acc[mt][nt], ah[mt], blf[h][pr], blf[h][pr + 1]);
                MMA16816(acc[mt][nt], al[mt], bhf[h][pr], bhf[h][pr + 1]);
            }
    }

    int l4 = l >> 2, l2 = (l & 3) << 1;
#pragma unroll
    for (int mt = 0; mt < 2; mt++)
#pragma unroll
        for (int half = 0; half < 2; half++) {
            int row = wm * 32 + mt * 16 + l4 + half * 8;
            __nv_bfloat16* ph = g_aoh + ((size_t)b * C_ + hg * HD + row) * NPIX + ntile * 128;
            __nv_bfloat16* pl = g_aol + ((size_t)b * C_ + hg * HD + row) * NPIX + ntile * 128;
#pragma unroll
            for (int nt = 0; nt < 4; nt++) {
                int col = wn * 32 + nt * 8 + l2;
                float v0 = acc[mt][nt][half * 2], v1 = acc[mt][nt][half * 2 + 1];
                __nv_bfloat16 h0, o0, h1, o1;
                split_f(v0, h0, o0); split_f(v1, h1, o1);
                *(uint32_t*)(ph + col) = pack2(h0, h1);
                *(uint32_t*)(pl + col) = pack2(o0, o1);
            }
        }
}

// ---------------- launch ----------------
extern "C" void kernel_launch(void* const* d_in, const int* in_sizes, int n_in,
                              void* d_out, int out_size) {
    const float* x  = (const float*)d_in[0];
    const float* dw = (const float*)d_in[1];
    const float* qw = (const float*)d_in[2];
    const float* kw = (const float*)d_in[3];
    const float* vw = (const float*)d_in[4];
    const float* pw = (const float*)d_in[5];
    float* out = (float*)d_out;

    __nv_bfloat16 *yhp, *ylp, *aohp, *aolp, *whp, *wlp;
    cudaGetSymbolAddress((void**)&yhp,  g_yh);
    cudaGetSymbolAddress((void**)&ylp,  g_yl);
    cudaGetSymbolAddress((void**)&aohp, g_aoh);
    cudaGetSymbolAddress((void**)&aolp, g_aol);
    cudaGetSymbolAddress((void**)&whp,  g_wh);
    cudaGetSymbolAddress((void**)&wlp,  g_wl);

    cudaFuncSetAttribute(gemm_hmma_kernel, cudaFuncAttributeMaxDynamicSharedMemorySize, GEMM_SMEM);
    cudaFuncSetAttribute(scores_kernel, cudaFuncAttributeMaxDynamicSharedMemorySize, SC_SMEM);
    cudaFuncSetAttribute(apply_kernel, cudaFuncAttributeMaxDynamicSharedMemorySize, AP_SMEM);

    zero_kernel<<<16, 256>>>();                                     // 1
    dwconv_kernel<<<dim3(NPIX / 256, B_ * C_), 256>>>(x, dw);       // 2
    convert_w_kernel<<<4096, 256>>>(qw, kw, vw, pw);                // 3
    // fused QKV GEMM, M=1536, M-tile 64 (profiled slot)
    gemm_hmma_kernel<<<dim3(NPIX / 128, 24, B_), 256, GEMM_SMEM>>>( // 4
        whp, wlp, yhp, ylp, nullptr, 1);
    scores_kernel<<<dim3(8, B_ * HEADS_), 256, SC_SMEM>>>();        // 5
    softmax_kernel<<<B_ * HEADS_, 256>>>();                         // 6
    apply_kernel<<<dim3(NPIX / 128, B_ * HEADS_), 256, AP_SMEM>>>();// 7
    // proj GEMM: weight rows [1536, 2048)
    gemm_hmma_kernel<<<dim3(NPIX / 128, 8, B_), 256, GEMM_SMEM>>>(  // 8
        whp + 1536 * C_, wlp + 1536 * C_, aohp, aolp, out, 0);
}

// round 7
// speedup vs baseline: 4.2966x; 1.4102x over previous
#include <cuda_runtime.h>
#include <cuda_fp16.h>
#include <math.h>
#include <stdint.h>

#define B_     8
#define C_     512
#define HH     64
#define WW     64
#define NPIX   4096
#define HEADS_ 8
#define HD     64
#define TOFF   (B_ * C_ * NPIX)

// ---------------- scratch ----------------
__device__ __align__(16) __half g_y [TOFF];                      // dwconv out (fp16)
__device__ __align__(16) __half g_q [TOFF], g_k[TOFF], g_v[TOFF];
__device__ __align__(16) __half g_ao[TOFF];
__device__ __align__(16) __half g_wh[4 * C_ * C_], g_wl[4 * C_ * C_];
__device__ __align__(16) __half g_at[B_ * HEADS_ * HD * HD];
__device__ float g_part[B_ * HEADS_ * 8 * HD * HD];
__device__ float g_sq[3 * B_ * C_];

// ---------------- PTX helpers (baseline sm_80+) ----------------
__device__ __forceinline__ uint32_t smem_u32(const void* p) {
    uint32_t a;
    asm("{ .reg .u64 t; cvta.to.shared.u64 t, %1; cvt.u32.u64 %0, t; }" : "=r"(a) : "l"(p));
    return a;
}
#define CP16(s, g) asm volatile("cp.async.cg.shared.global [%0], [%1], 16;" :: "r"(s), "l"(g))
#define CP_COMMIT() asm volatile("cp.async.commit_group;" ::: "memory")
#define CP_WAIT2()  asm volatile("cp.async.wait_group 2;" ::: "memory")
#define CP_WAIT1()  asm volatile("cp.async.wait_group 1;" ::: "memory")
#define CP_WAIT0()  asm volatile("cp.async.wait_group 0;" ::: "memory")

#define LDSM_X4(r, a) \
    asm volatile("ldmatrix.sync.aligned.m8n8.x4.shared.b16 {%0,%1,%2,%3}, [%4];" \
        : "=r"((r)[0]), "=r"((r)[1]), "=r"((r)[2]), "=r"((r)[3]) : "r"(a))
#define LDSM_X4T(r, a) \
    asm volatile("ldmatrix.sync.aligned.m8n8.x4.trans.shared.b16 {%0,%1,%2,%3}, [%4];" \
        : "=r"((r)[0]), "=r"((r)[1]), "=r"((r)[2]), "=r"((r)[3]) : "r"(a))
#define MMA16816(d, a, b0, b1) \
    asm volatile("mma.sync.aligned.m16n8k16.row.col.f32.f16.f16.f32 " \
        "{%0,%1,%2,%3}, {%4,%5,%6,%7}, {%8,%9}, {%0,%1,%2,%3};" \
        : "+f"((d)[0]), "+f"((d)[1]), "+f"((d)[2]), "+f"((d)[3]) \
        : "r"((a)[0]), "r"((a)[1]), "r"((a)[2]), "r"((a)[3]), "r"(b0), "r"(b1))

__device__ __forceinline__ uint32_t sw128(uint32_t o) { return o ^ ((o >> 3) & 0x70); }

__device__ __forceinline__ void split_h(float v, __half& hi, __half& lo) {
    hi = __float2half_rn(v);
    lo = __float2half_rn(v - __half2float(hi));
}
__device__ __forceinline__ uint32_t pack2h(__half a, __half b) {
    unsigned short ua = *(unsigned short*)&a, ub = *(unsigned short*)&b;
    return (uint32_t)ua | ((uint32_t)ub << 16);
}
__device__ __forceinline__ float inv_norm(float s) {
    return 1.0f / fmaxf(sqrtf(s), 1e-12f);
}

// ---------------- zero sumsq ----------------
__global__ __launch_bounds__(256) void zero_kernel() {
    for (int i = blockIdx.x * 256 + threadIdx.x; i < 3 * B_ * C_; i += gridDim.x * 256)
        g_sq[i] = 0.f;
}

// ---------------- depthwise 3x3 -> fp16 ----------------
__global__ __launch_bounds__(256) void dwconv_kernel(const float* __restrict__ x,
                                                     const float* __restrict__ w) {
    int plane = blockIdx.y;
    int c = plane & (C_ - 1);
    __shared__ float ws[9];
    if (threadIdx.x < 9) ws[threadIdx.x] = w[c * 9 + threadIdx.x];
    __syncthreads();
    int p = blockIdx.x * 256 + threadIdx.x;
    int h = p >> 6, wc = p & 63;
    const float* xp = x + (size_t)plane * NPIX;
    float acc = 0.f;
#pragma unroll
    for (int kh = 0; kh < 3; kh++) {
        int hh = h + kh - 1;
        if (hh < 0 || hh >= HH) continue;
#pragma unroll
        for (int kw = 0; kw < 3; kw++) {
            int wcol = wc + kw - 1;
            if (wcol < 0 || wcol >= WW) continue;
            acc = fmaf(ws[kh * 3 + kw], xp[hh * WW + wcol], acc);
        }
    }
    g_y[(size_t)plane * NPIX + p] = __float2half_rn(acc);
}

// ---------------- weight conversion: stacked [q;k;v;proj] -> fp16 hi/lo ----------------
__global__ __launch_bounds__(256) void convert_w_kernel(const float* __restrict__ qw,
                                                        const float* __restrict__ kw,
                                                        const float* __restrict__ vw,
                                                        const float* __restrict__ pw) {
    int idx = blockIdx.x * 256 + threadIdx.x;
    int m = idx >> 18;
    const float* src = (m == 0) ? qw : (m == 1) ? kw : (m == 2) ? vw : pw;
    float v = src[idx & 262143];
    __half hi, lo;
    split_h(v, hi, lo);
    g_wh[idx] = hi;
    g_wl[idx] = lo;
}

// ---------------- fp16 HMMA GEMM: W split 2-term, B single. 3-stage pipeline ----------------
#define A_HI 0
#define A_LO 8192
#define B_S  16384
#define STAGE 32768
#define GEMM_SMEM (3 * STAGE)

__global__ __launch_bounds__(256, 2) void gemm_hmma_kernel(const __half* __restrict__ Wh,
                                                           const __half* __restrict__ Wl,
                                                           const __half* __restrict__ Bg,
                                                           float* __restrict__ Cout,
                                                           int qkv_mode) {
    extern __shared__ char smem[];
    uint32_t sb = smem_u32(smem);
    int tid = threadIdx.x;
    int l = tid & 31, wid = tid >> 5;
    int wm = wid & 1, wn = wid >> 1;        // warp tile: 32 rows x 32 cols
    int bn = blockIdx.x * 128;
    int bm = blockIdx.y * 64;
    int bz = blockIdx.z;
    const __half* Bp = Bg + (size_t)bz * C_ * NPIX;

    auto load_chunk = [&](int chunk, int stg) {
        uint32_t st = sb + stg * STAGE;
        int k0 = chunk * 64;
#pragma unroll
        for (int it = 0; it < 2; it++) {
            int idx = tid + it * 256;              // 0..511
            int ar = idx >> 3;                     // 0..63
            int ac = (idx & 7) << 3;
            uint32_t aswo = sw128((uint32_t)(ar * 128 + ac * 2));
            CP16(st + A_HI + aswo, Wh + (size_t)(bm + ar) * C_ + k0 + ac);
            CP16(st + A_LO + aswo, Wl + (size_t)(bm + ar) * C_ + k0 + ac);
        }
#pragma unroll
        for (int it = 0; it < 4; it++) {
            int idx = tid + it * 256;              // 0..1023
            int brr = idx >> 4;                    // 0..63
            int bnn = (idx & 15) << 3;             // 0..120
            int s = bnn >> 6, nl = bnn & 63;
            uint32_t bswo = (uint32_t)(s * 8192) + sw128((uint32_t)(brr * 128 + nl * 2));
            CP16(st + B_S + bswo, Bp + (size_t)(k0 + brr) * NPIX + bn + bnn);
        }
    };

    float acc[2][4][4] = {};
    int lr = l & 15;
    int lc = (l >> 4) << 4;

    load_chunk(0, 0); CP_COMMIT();
    load_chunk(1, 1); CP_COMMIT();
    load_chunk(2, 2); CP_COMMIT();

    for (int chunk = 0; chunk < 8; chunk++) {
        CP_WAIT2();
        __syncthreads();
        int stg = chunk % 3;
        uint32_t st = sb + stg * STAGE;
#pragma unroll
        for (int k16 = 0; k16 < 4; k16++) {
            uint32_t ah[2][4], al[2][4], bf[2][4];
            int kb = k16 * 32 + lc;
#pragma unroll
            for (int mt = 0; mt < 2; mt++) {
                uint32_t swo = sw128((uint32_t)((wm * 32 + mt * 16 + lr) * 128 + kb));
                LDSM_X4(ah[mt], st + A_HI + swo);
                LDSM_X4(al[mt], st + A_LO + swo);
            }
            uint32_t pb = (uint32_t)((wn >> 1) * 8192);
#pragma unroll
            for (int h = 0; h < 2; h++) {
                uint32_t swo = sw128((uint32_t)((k16 * 16 + lr) * 128 + (wn & 1) * 64 + h * 32 + lc));
                LDSM_X4T(bf[h], st + B_S + pb + swo);
            }
#pragma unroll
            for (int mt = 0; mt < 2; mt++) {
#pragma unroll
                for (int nt = 0; nt < 4; nt++) {
                    int h = nt >> 1, pr = (nt & 1) * 2;
                    MMA16816(acc[mt][nt], ah[mt], bf[h][pr], bf[h][pr + 1]);
                    MMA16816(acc[mt][nt], al[mt], bf[h][pr], bf[h][pr + 1]);
                }
            }
        }
        __syncthreads();
        if (chunk + 3 < 8) load_chunk(chunk + 3, (chunk + 3) % 3);
        CP_COMMIT();
    }

    int l4 = l >> 2, l2 = (l & 3) << 1;
    if (qkv_mode) {
#pragma unroll
        for (int mt = 0; mt < 2; mt++) {
#pragma unroll
            for (int half = 0; half < 2; half++) {
                int row = bm + wm * 32 + mt * 16 + l4 + half * 8;
                int which = row >> 9, ml = row & 511;
                __half* pq = ((which == 0) ? g_q : (which == 1) ? g_k : g_v)
                             + ((size_t)bz * C_ + ml) * NPIX;
                float ss = 0.f;
#pragma unroll
                for (int nt = 0; nt < 4; nt++) {
                    int col = bn + wn * 32 + nt * 8 + l2;
                    float v0 = acc[mt][nt][half * 2], v1 = acc[mt][nt][half * 2 + 1];
                    ss += v0 * v0 + v1 * v1;
                    *(uint32_t*)(pq + col) = pack2h(__float2half_rn(v0), __float2half_rn(v1));
                }
                ss += __shfl_xor_sync(0xffffffffu, ss, 1);
                ss += __shfl_xor_sync(0xffffffffu, ss, 2);
                if ((l & 3) == 0)
                    atomicAdd(&g_sq[which * (B_ * C_) + bz * C_ + ml], ss);
            }
        }
    } else {
#pragma unroll
        for (int mt = 0; mt < 2; mt++) {
#pragma unroll
            for (int half = 0; half < 2; half++) {
                int row = bm + wm * 32 + mt * 16 + l4 + half * 8;
                float* base = Cout + ((size_t)bz * C_ + row) * NPIX;
#pragma unroll
                for (int nt = 0; nt < 4; nt++) {
                    int col = bn + wn * 32 + nt * 8 + l2;
                    *(float2*)(base + col) =
                        make_float2(acc[mt][nt][half * 2], acc[mt][nt][half * 2 + 1]);
                }
            }
        }
    }
}

// ---------------- scores: fp16 HMMA, split-K partials ----------------
#define SC_Q 0
#define SC_K 8192
#define SC_STAGE 16384
#define SC_SMEM (2 * SC_STAGE)

__global__ __launch_bounds__(256) void scores_kernel() {
    extern __shared__ char smem[];
    uint32_t sb = smem_u32(smem);
    int sp = blockIdx.x, bh = blockIdx.y;
    int b = bh >> 3, hg = bh & 7;
    int tid = threadIdx.x, l = tid & 31, wid = tid >> 5;
    int wm = wid & 1, wn = wid >> 1;
    const __half* qp = g_q + ((size_t)b * C_ + hg * HD) * NPIX;
    const __half* kp = g_k + ((size_t)b * C_ + hg * HD) * NPIX;
    int px0 = sp * 512;

    auto load_chunk = [&](int chunk, int stg) {
        uint32_t st = sb + stg * SC_STAGE;
        int k0 = px0 + chunk * 64;
#pragma unroll
        for (int it = 0; it < 2; it++) {
            int idx = tid + it * 256;
            int r = idx >> 3;
            int c8 = idx & 7;
            uint32_t swo = sw128((uint32_t)(r * 128 + c8 * 16));
            size_t go = (size_t)r * NPIX + k0 + c8 * 8;
            CP16(st + SC_Q + swo, qp + go);
            CP16(st + SC_K + swo, kp + go);
        }
    };

    float acc[2][2][4] = {};
    int lr = l & 15, lc = (l >> 4) << 4;
    int bn_row = wn * 16 + (l & 7) + ((l >> 4) << 3);
    int bn_kb = ((l >> 3) & 1) * 16;

    load_chunk(0, 0); CP_COMMIT();
    load_chunk(1, 1); CP_COMMIT();

    for (int chunk = 0; chunk < 8; chunk++) {
        CP_WAIT1();
        __syncthreads();
        uint32_t st = sb + (chunk & 1) * SC_STAGE;
#pragma unroll
        for (int k16 = 0; k16 < 4; k16++) {
            uint32_t ah[2][4], bf[4];
#pragma unroll
            for (int mt = 0; mt < 2; mt++) {
                uint32_t swo = sw128((uint32_t)((wm * 32 + mt * 16 + lr) * 128 + k16 * 32 + lc));
                LDSM_X4(ah[mt], st + SC_Q + swo);
            }
            uint32_t swb = sw128((uint32_t)(bn_row * 128 + k16 * 32 + bn_kb));
            LDSM_X4(bf, st + SC_K + swb);
#pragma unroll
            for (int mt = 0; mt < 2; mt++)
#pragma unroll
                for (int nt = 0; nt < 2; nt++)
                    MMA16816(acc[mt][nt], ah[mt], bf[nt * 2], bf[nt * 2 + 1]);
        }
        __syncthreads();
        if (chunk + 2 < 8) load_chunk(chunk + 2, chunk & 1);
        CP_COMMIT();
    }

    float* op = g_part + ((size_t)bh * 8 + sp) * 4096;
    int l4 = l >> 2, l2 = (l & 3) << 1;
#pragma unroll
    for (int mt = 0; mt < 2; mt++)
#pragma unroll
        for (int half = 0; half < 2; half++) {
            int row = wm * 32 + mt * 16 + l4 + half * 8;
#pragma unroll
            for (int nt = 0; nt < 2; nt++) {
                int col = wn * 16 + nt * 8 + l2;
                *(float2*)(op + row * 64 + col) =
                    make_float2(acc[mt][nt][half * 2], acc[mt][nt][half * 2 + 1]);
            }
        }
}

// ---------------- reduce + softmax, fold norms, -> attn fp16 ----------------
__global__ __launch_bounds__(256) void softmax_kernel() {
    int bh = blockIdx.x;
    int b = bh >> 3, hg = bh & 7;
    int cb = b * C_ + hg * HD;
    __shared__ float Ss[64][64];
    __shared__ float rv_s[64];
    int tid = threadIdx.x;
    const float scale = 0.125f;
    if (tid < 64) rv_s[tid] = inv_norm(g_sq[2 * B_ * C_ + cb + tid]);
    for (int i = tid; i < 4096; i += 256) {
        float s = 0.f;
#pragma unroll
        for (int p = 0; p < 8; p++) s += g_part[((size_t)bh * 8 + p) * 4096 + i];
        int r = i >> 6, c = i & 63;
        Ss[r][c] = s * inv_norm(g_sq[cb + r]) * scale * inv_norm(g_sq[B_ * C_ + cb + c]);
    }
    __syncthreads();
    int warp = tid >> 5, lane = tid & 31;
#pragma unroll
    for (int rr = 0; rr < 8; rr++) {
        int r = warp * 8 + rr;
        float v0 = Ss[r][lane], v1 = Ss[r][lane + 32];
        float m = fmaxf(v0, v1);
#pragma unroll
        for (int off = 16; off; off >>= 1) m = fmaxf(m, __shfl_xor_sync(0xffffffffu, m, off));
        float e0 = __expf(v0 - m), e1 = __expf(v1 - m);
        float s = e0 + e1;
#pragma unroll
        for (int off = 16; off; off >>= 1) s += __shfl_xor_sync(0xffffffffu, s, off);
        float inv = 1.0f / s;
        size_t base = (size_t)bh * 4096 + r * 64;
        g_at[base + lane]      = __float2half_rn(e0 * inv * rv_s[lane]);
        g_at[base + lane + 32] = __float2half_rn(e1 * inv * rv_s[lane + 32]);
    }
}

// ---------------- apply: fp16 HMMA out = attn @ v -> ao fp16 ----------------
#define AP_A 0
#define AP_V 8192
#define AP_SMEM 24576

__global__ __launch_bounds__(256) void apply_kernel() {
    extern __shared__ char smem[];
    uint32_t sb = smem_u32(smem);
    int ntile = blockIdx.x;
    int bh = blockIdx.y;
    int b = bh >> 3, hg = bh & 7;
    int tid = threadIdx.x, l = tid & 31, wid = tid >> 5;
    int wm = wid & 1, wn = wid >> 1;

#pragma unroll
    for (int it = 0; it < 2; it++) {
        int idx = tid + it * 256;
        int r = idx >> 3, c8 = idx & 7;
        uint32_t swo = sw128((uint32_t)(r * 128 + c8 * 16));
        CP16(sb + AP_A + swo, g_at + (size_t)bh * 4096 + r * 64 + c8 * 8);
    }
    const __half* vp = g_v + ((size_t)b * C_ + hg * HD) * NPIX + ntile * 128;
#pragma unroll
    for (int it = 0; it < 4; it++) {
        int idx = tid + it * 256;
        int r = idx >> 4;
        int n8 = idx & 15;
        int s = n8 >> 3, nl = n8 & 7;
        uint32_t swo = (uint32_t)(s * 8192) + sw128((uint32_t)(r * 128 + nl * 16));
        CP16(sb + AP_V + swo, vp + (size_t)r * NPIX + n8 * 8);
    }
    CP_COMMIT();
    CP_WAIT0();
    __syncthreads();

    float acc[2][4][4] = {};
    int lr = l & 15, lc = (l >> 4) << 4;
#pragma unroll
    for (int k16 = 0; k16 < 4; k16++) {
        uint32_t ah[2][4], bf[2][4];
#pragma unroll
        for (int mt = 0; mt < 2; mt++) {
            uint32_t swo = sw128((uint32_t)((wm * 32 + mt * 16 + lr) * 128 + k16 * 32 + lc));
            LDSM_X4(ah[mt], sb + AP_A + swo);
        }
        uint32_t pb = (uint32_t)((wn >> 1) * 8192);
#pragma unroll
        for (int h = 0; h < 2; h++) {
            uint32_t swo = sw128((uint32_t)((k16 * 16 + lr) * 128 + (wn & 1) * 64 + h * 32 + lc));
            LDSM_X4T(bf[h], sb + AP_V + pb + swo);
        }
#pragma unroll
        for (int mt = 0; mt < 2; mt++)
#pragma unroll
            for (int nt = 0; nt < 4; nt++) {
                int h = nt >> 1, pr = (nt & 1) * 2;
                MMA16816(acc[mt][nt], ah[mt], bf[h][pr], bf[h][pr + 1]);
            }
    }

    int l4 = l >> 2, l2 = (l & 3) << 1;
#pragma unroll
    for (int mt = 0; mt < 2; mt++)
#pragma unroll
        for (int half = 0; half < 2; half++) {
            int row = wm * 32 + mt * 16 + l4 + half * 8;
            __half* po = g_ao + ((size_t)b * C_ + hg * HD + row) * NPIX + ntile * 128;
#pragma unroll
            for (int nt = 0; nt < 4; nt++) {
                int col = wn * 32 + nt * 8 + l2;
                *(uint32_t*)(po + col) =
                    pack2h(__float2half_rn(acc[mt][nt][half * 2]),
                           __float2half_rn(acc[mt][nt][half * 2 + 1]));
            }
        }
}

// ---------------- launch ----------------
extern "C" void kernel_launch(void* const* d_in, const int* in_sizes, int n_in,
                              void* d_out, int out_size) {
    const float* x  = (const float*)d_in[0];
    const float* dw = (const float*)d_in[1];
    const float* qw = (const float*)d_in[2];
    const float* kw = (const float*)d_in[3];
    const float* vw = (const float*)d_in[4];
    const float* pw = (const float*)d_in[5];
    float* out = (float*)d_out;

    __half *yp, *aop, *whp, *wlp;
    cudaGetSymbolAddress((void**)&yp,  g_y);
    cudaGetSymbolAddress((void**)&aop, g_ao);
    cudaGetSymbolAddress((void**)&whp, g_wh);
    cudaGetSymbolAddress((void**)&wlp, g_wl);

    cudaFuncSetAttribute(gemm_hmma_kernel, cudaFuncAttributeMaxDynamicSharedMemorySize, GEMM_SMEM);
    cudaFuncSetAttribute(scores_kernel, cudaFuncAttributeMaxDynamicSharedMemorySize, SC_SMEM);
    cudaFuncSetAttribute(apply_kernel, cudaFuncAttributeMaxDynamicSharedMemorySize, AP_SMEM);

    zero_kernel<<<16, 256>>>();                                     // 1
    dwconv_kernel<<<dim3(NPIX / 256, B_ * C_), 256>>>(x, dw);       // 2
    convert_w_kernel<<<4096, 256>>>(qw, kw, vw, pw);                // 3
    // fused QKV GEMM, M=1536, M-tile 64 (profiled slot)
    gemm_hmma_kernel<<<dim3(NPIX / 128, 24, B_), 256, GEMM_SMEM>>>( // 4
        whp, wlp, yp, nullptr, 1);
    scores_kernel<<<dim3(8, B_ * HEADS_), 256, SC_SMEM>>>();        // 5
    softmax_kernel<<<B_ * HEADS_, 256>>>();                         // 6
    apply_kernel<<<dim3(NPIX / 128, B_ * HEADS_), 256, AP_SMEM>>>();// 7
    // proj GEMM: weight rows [1536, 2048)
    gemm_hmma_kernel<<<dim3(NPIX / 128, 8, B_), 256, GEMM_SMEM>>>(  // 8
        whp + 1536 * C_, wlp + 1536 * C_, aop, out, 0);
}

// round 8
// speedup vs baseline: 5.2531x; 1.2226x over previous
#include <cuda_runtime.h>
#include <cuda_fp16.h>
#include <math.h>
#include <stdint.h>

#define B_     8
#define C_     512
#define HH     64
#define WW     64
#define NPIX   4096
#define HEADS_ 8
#define HD     64
#define TOFF   (B_ * C_ * NPIX)

// ---------------- scratch ----------------
__device__ __align__(16) __half g_y [TOFF];
__device__ __align__(16) __half g_q [TOFF], g_k[TOFF], g_v[TOFF];
__device__ __align__(16) __half g_ao[TOFF];
__device__ __align__(16) __half g_wh[4 * C_ * C_], g_wl[4 * C_ * C_];
__device__ __align__(16) __half g_at[B_ * HEADS_ * HD * HD];
__device__ float g_part[B_ * HEADS_ * 8 * HD * HD];
__device__ float g_sq[3 * B_ * C_];

// ---------------- PTX helpers (baseline sm_80+) ----------------
__device__ __forceinline__ uint32_t smem_u32(const void* p) {
    uint32_t a;
    asm("{ .reg .u64 t; cvta.to.shared.u64 t, %1; cvt.u32.u64 %0, t; }" : "=r"(a) : "l"(p));
    return a;
}
#define CP16(s, g) asm volatile("cp.async.cg.shared.global [%0], [%1], 16;" :: "r"(s), "l"(g))
#define CP_COMMIT() asm volatile("cp.async.commit_group;" ::: "memory")
#define CP_WAIT(n)  asm volatile("cp.async.wait_group %0;" :: "n"(n) : "memory")
#define CP_WAIT0()  asm volatile("cp.async.wait_group 0;" ::: "memory")

#define LDSM_X4(r, a) \
    asm volatile("ldmatrix.sync.aligned.m8n8.x4.shared.b16 {%0,%1,%2,%3}, [%4];" \
        : "=r"((r)[0]), "=r"((r)[1]), "=r"((r)[2]), "=r"((r)[3]) : "r"(a))
#define LDSM_X4T(r, a) \
    asm volatile("ldmatrix.sync.aligned.m8n8.x4.trans.shared.b16 {%0,%1,%2,%3}, [%4];" \
        : "=r"((r)[0]), "=r"((r)[1]), "=r"((r)[2]), "=r"((r)[3]) : "r"(a))
#define MMA16816(d, a, b0, b1) \
    asm volatile("mma.sync.aligned.m16n8k16.row.col.f32.f16.f16.f32 " \
        "{%0,%1,%2,%3}, {%4,%5,%6,%7}, {%8,%9}, {%0,%1,%2,%3};" \
        : "+f"((d)[0]), "+f"((d)[1]), "+f"((d)[2]), "+f"((d)[3]) \
        : "r"((a)[0]), "r"((a)[1]), "r"((a)[2]), "r"((a)[3]), "r"(b0), "r"(b1))

__device__ __forceinline__ uint32_t sw128(uint32_t o) { return o ^ ((o >> 3) & 0x70); }

__device__ __forceinline__ void split_h(float v, __half& hi, __half& lo) {
    hi = __float2half_rn(v);
    lo = __float2half_rn(v - __half2float(hi));
}
__device__ __forceinline__ uint32_t pack2h(__half a, __half b) {
    unsigned short ua = *(unsigned short*)&a, ub = *(unsigned short*)&b;
    return (uint32_t)ua | ((uint32_t)ub << 16);
}
__device__ __forceinline__ float inv_norm(float s) {
    return 1.0f / fmaxf(sqrtf(s), 1e-12f);
}

// ---------------- zero sumsq ----------------
__global__ __launch_bounds__(256) void zero_kernel() {
    for (int i = blockIdx.x * 256 + threadIdx.x; i < 3 * B_ * C_; i += gridDim.x * 256)
        g_sq[i] = 0.f;
}

// ---------------- depthwise 3x3 -> fp16 ----------------
__global__ __launch_bounds__(256) void dwconv_kernel(const float* __restrict__ x,
                                                     const float* __restrict__ w) {
    int plane = blockIdx.y;
    int c = plane & (C_ - 1);
    __shared__ float ws[9];
    if (threadIdx.x < 9) ws[threadIdx.x] = w[c * 9 + threadIdx.x];
    __syncthreads();
    int p = blockIdx.x * 256 + threadIdx.x;
    int h = p >> 6, wc = p & 63;
    const float* xp = x + (size_t)plane * NPIX;
    float acc = 0.f;
#pragma unroll
    for (int kh = 0; kh < 3; kh++) {
        int hh = h + kh - 1;
        if (hh < 0 || hh >= HH) continue;
#pragma unroll
        for (int kw = 0; kw < 3; kw++) {
            int wcol = wc + kw - 1;
            if (wcol < 0 || wcol >= WW) continue;
            acc = fmaf(ws[kh * 3 + kw], xp[hh * WW + wcol], acc);
        }
    }
    g_y[(size_t)plane * NPIX + p] = __float2half_rn(acc);
}

// ---------------- weight conversion: stacked [q;k;v;proj] -> fp16 hi/lo ----------------
__global__ __launch_bounds__(256) void convert_w_kernel(const float* __restrict__ qw,
                                                        const float* __restrict__ kw,
                                                        const float* __restrict__ vw,
                                                        const float* __restrict__ pw) {
    int idx = blockIdx.x * 256 + threadIdx.x;
    int m = idx >> 18;
    const float* src = (m == 0) ? qw : (m == 1) ? kw : (m == 2) ? vw : pw;
    float v = src[idx & 262143];
    __half hi, lo;
    split_h(v, hi, lo);
    g_wh[idx] = hi;
    g_wl[idx] = lo;
}

// ---------------- fp16 HMMA GEMM, templated on weight terms ----------------
// TERMS=1: stage 24KB (A 8K + B 16K), 4 stages. TERMS=2: stage 32KB, 3 stages.
template <int TERMS>
__global__ __launch_bounds__(256, 2) void gemm_hmma_kernel(const __half* __restrict__ Wh,
                                                           const __half* __restrict__ Wl,
                                                           const __half* __restrict__ Bg,
                                                           float* __restrict__ Cout,
                                                           int qkv_mode) {
    constexpr int A_LO_OFF = 8192;                       // valid when TERMS==2
    constexpr int B_OFF    = (TERMS == 2) ? 16384 : 8192;
    constexpr int STAGE    = (TERMS == 2) ? 32768 : 24576;
    constexpr int NSTAGES  = (TERMS == 2) ? 3 : 4;

    extern __shared__ char smem[];
    uint32_t sb = smem_u32(smem);
    int tid = threadIdx.x;
    int l = tid & 31, wid = tid >> 5;
    int wm = wid & 1, wn = wid >> 1;        // warp tile: 32 rows x 32 cols
    int bn = blockIdx.x * 128;
    int bm = blockIdx.y * 64;
    int bz = blockIdx.z;
    const __half* Bp = Bg + (size_t)bz * C_ * NPIX;

    auto load_chunk = [&](int chunk, int stg) {
        uint32_t st = sb + stg * STAGE;
        int k0 = chunk * 64;
#pragma unroll
        for (int it = 0; it < 2; it++) {
            int idx = tid + it * 256;              // 0..511
            int ar = idx >> 3;                     // 0..63
            int ac = (idx & 7) << 3;
            uint32_t aswo = sw128((uint32_t)(ar * 128 + ac * 2));
            CP16(st + aswo, Wh + (size_t)(bm + ar) * C_ + k0 + ac);
            if (TERMS == 2)
                CP16(st + A_LO_OFF + aswo, Wl + (size_t)(bm + ar) * C_ + k0 + ac);
        }
#pragma unroll
        for (int it = 0; it < 4; it++) {
            int idx = tid + it * 256;              // 0..1023
            int brr = idx >> 4;                    // 0..63
            int bnn = (idx & 15) << 3;             // 0..120
            int s = bnn >> 6, nl = bnn & 63;
            uint32_t bswo = (uint32_t)(s * 8192) + sw128((uint32_t)(brr * 128 + nl * 2));
            CP16(st + B_OFF + bswo, Bp + (size_t)(k0 + brr) * NPIX + bn + bnn);
        }
    };

    float acc[2][4][4] = {};
    int lr = l & 15;
    int lc = (l >> 4) << 4;

#pragma unroll
    for (int pf = 0; pf < NSTAGES - 1; pf++) {
        load_chunk(pf, pf);
        CP_COMMIT();
    }

    for (int chunk = 0; chunk < 8; chunk++) {
        CP_WAIT(NSTAGES - 2);
        __syncthreads();
        int stg = chunk % NSTAGES;
        uint32_t st = sb + stg * STAGE;
#pragma unroll
        for (int k16 = 0; k16 < 4; k16++) {
            uint32_t ah[2][4], al[2][4], bf[2][4];
            int kb = k16 * 32 + lc;
#pragma unroll
            for (int mt = 0; mt < 2; mt++) {
                uint32_t swo = sw128((uint32_t)((wm * 32 + mt * 16 + lr) * 128 + kb));
                LDSM_X4(ah[mt], st + swo);
                if (TERMS == 2) LDSM_X4(al[mt], st + A_LO_OFF + swo);
            }
            uint32_t pb = (uint32_t)((wn >> 1) * 8192);
#pragma unroll
            for (int h = 0; h < 2; h++) {
                uint32_t swo = sw128((uint32_t)((k16 * 16 + lr) * 128 + (wn & 1) * 64 + h * 32 + lc));
                LDSM_X4T(bf[h], st + B_OFF + pb + swo);
            }
#pragma unroll
            for (int mt = 0; mt < 2; mt++) {
#pragma unroll
                for (int nt = 0; nt < 4; nt++) {
                    int h = nt >> 1, pr = (nt & 1) * 2;
                    MMA16816(acc[mt][nt], ah[mt], bf[h][pr], bf[h][pr + 1]);
                    if (TERMS == 2)
                        MMA16816(acc[mt][nt], al[mt], bf[h][pr], bf[h][pr + 1]);
                }
            }
        }
        __syncthreads();
        if (chunk + NSTAGES - 1 < 8)
            load_chunk(chunk + NSTAGES - 1, (chunk + NSTAGES - 1) % NSTAGES);
        CP_COMMIT();
    }

    int l4 = l >> 2, l2 = (l & 3) << 1;
    if (qkv_mode) {
#pragma unroll
        for (int mt = 0; mt < 2; mt++) {
#pragma unroll
            for (int half = 0; half < 2; half++) {
                int row = bm + wm * 32 + mt * 16 + l4 + half * 8;
                int which = row >> 9, ml = row & 511;
                __half* pq = ((which == 0) ? g_q : (which == 1) ? g_k : g_v)
                             + ((size_t)bz * C_ + ml) * NPIX;
                float ss = 0.f;
#pragma unroll
                for (int nt = 0; nt < 4; nt++) {
                    int col = bn + wn * 32 + nt * 8 + l2;
                    float v0 = acc[mt][nt][half * 2], v1 = acc[mt][nt][half * 2 + 1];
                    ss += v0 * v0 + v1 * v1;
                    *(uint32_t*)(pq + col) = pack2h(__float2half_rn(v0), __float2half_rn(v1));
                }
                ss += __shfl_xor_sync(0xffffffffu, ss, 1);
                ss += __shfl_xor_sync(0xffffffffu, ss, 2);
                if ((l & 3) == 0)
                    atomicAdd(&g_sq[which * (B_ * C_) + bz * C_ + ml], ss);
            }
        }
    } else {
#pragma unroll
        for (int mt = 0; mt < 2; mt++) {
#pragma unroll
            for (int half = 0; half < 2; half++) {
                int row = bm + wm * 32 + mt * 16 + l4 + half * 8;
                float* base = Cout + ((size_t)bz * C_ + row) * NPIX;
#pragma unroll
                for (int nt = 0; nt < 4; nt++) {
                    int col = bn + wn * 32 + nt * 8 + l2;
                    *(float2*)(base + col) =
                        make_float2(acc[mt][nt][half * 2], acc[mt][nt][half * 2 + 1]);
                }
            }
        }
    }
}

// ---------------- scores: fp16 HMMA, split-K partials ----------------
#define SC_Q 0
#define SC_K 8192
#define SC_STAGE 16384
#define SC_SMEM (2 * SC_STAGE)

__global__ __launch_bounds__(256) void scores_kernel() {
    extern __shared__ char smem[];
    uint32_t sb = smem_u32(smem);
    int sp = blockIdx.x, bh = blockIdx.y;
    int b = bh >> 3, hg = bh & 7;
    int tid = threadIdx.x, l = tid & 31, wid = tid >> 5;
    int wm = wid & 1, wn = wid >> 1;
    const __half* qp = g_q + ((size_t)b * C_ + hg * HD) * NPIX;
    const __half* kp = g_k + ((size_t)b * C_ + hg * HD) * NPIX;
    int px0 = sp * 512;

    auto load_chunk = [&](int chunk, int stg) {
        uint32_t st = sb + stg * SC_STAGE;
        int k0 = px0 + chunk * 64;
#pragma unroll
        for (int it = 0; it < 2; it++) {
            int idx = tid + it * 256;
            int r = idx >> 3;
            int c8 = idx & 7;
            uint32_t swo = sw128((uint32_t)(r * 128 + c8 * 16));
            size_t go = (size_t)r * NPIX + k0 + c8 * 8;
            CP16(st + SC_Q + swo, qp + go);
            CP16(st + SC_K + swo, kp + go);
        }
    };

    float acc[2][2][4] = {};
    int lr = l & 15, lc = (l >> 4) << 4;
    int bn_row = wn * 16 + (l & 7) + ((l >> 4) << 3);
    int bn_kb = ((l >> 3) & 1) * 16;

    load_chunk(0, 0); CP_COMMIT();
    load_chunk(1, 1); CP_COMMIT();

    for (int chunk = 0; chunk < 8; chunk++) {
        CP_WAIT(1);
        __syncthreads();
        uint32_t st = sb + (chunk & 1) * SC_STAGE;
#pragma unroll
        for (int k16 = 0; k16 < 4; k16++) {
            uint32_t ah[2][4], bf[4];
#pragma unroll
            for (int mt = 0; mt < 2; mt++) {
                uint32_t swo = sw128((uint32_t)((wm * 32 + mt * 16 + lr) * 128 + k16 * 32 + lc));
                LDSM_X4(ah[mt], st + SC_Q + swo);
            }
            uint32_t swb = sw128((uint32_t)(bn_row * 128 + k16 * 32 + bn_kb));
            LDSM_X4(bf, st + SC_K + swb);
#pragma unroll
            for (int mt = 0; mt < 2; mt++)
#pragma unroll
                for (int nt = 0; nt < 2; nt++)
                    MMA16816(acc[mt][nt], ah[mt], bf[nt * 2], bf[nt * 2 + 1]);
        }
        __syncthreads();
        if (chunk + 2 < 8) load_chunk(chunk + 2, chunk & 1);
        CP_COMMIT();
    }

    float* op = g_part + ((size_t)bh * 8 + sp) * 4096;
    int l4 = l >> 2, l2 = (l & 3) << 1;
#pragma unroll
    for (int mt = 0; mt < 2; mt++)
#pragma unroll
        for (int half = 0; half < 2; half++) {
            int row = wm * 32 + mt * 16 + l4 + half * 8;
#pragma unroll
            for (int nt = 0; nt < 2; nt++) {
                int col = wn * 16 + nt * 8 + l2;
                *(float2*)(op + row * 64 + col) =
                    make_float2(acc[mt][nt][half * 2], acc[mt][nt][half * 2 + 1]);
            }
        }
}

// ---------------- reduce + softmax, fold norms, -> attn fp16 ----------------
__global__ __launch_bounds__(256) void softmax_kernel() {
    int bh = blockIdx.x;
    int b = bh >> 3, hg = bh & 7;
    int cb = b * C_ + hg * HD;
    __shared__ float Ss[64][64];
    __shared__ float rv_s[64];
    int tid = threadIdx.x;
    const float scale = 0.125f;
    if (tid < 64) rv_s[tid] = inv_norm(g_sq[2 * B_ * C_ + cb + tid]);
    for (int i = tid; i < 4096; i += 256) {
        float s = 0.f;
#pragma unroll
        for (int p = 0; p < 8; p++) s += g_part[((size_t)bh * 8 + p) * 4096 + i];
        int r = i >> 6, c = i & 63;
        Ss[r][c] = s * inv_norm(g_sq[cb + r]) * scale * inv_norm(g_sq[B_ * C_ + cb + c]);
    }
    __syncthreads();
    int warp = tid >> 5, lane = tid & 31;
#pragma unroll
    for (int rr = 0; rr < 8; rr++) {
        int r = warp * 8 + rr;
        float v0 = Ss[r][lane], v1 = Ss[r][lane + 32];
        float m = fmaxf(v0, v1);
#pragma unroll
        for (int off = 16; off; off >>= 1) m = fmaxf(m, __shfl_xor_sync(0xffffffffu, m, off));
        float e0 = __expf(v0 - m), e1 = __expf(v1 - m);
        float s = e0 + e1;
#pragma unroll
        for (int off = 16; off; off >>= 1) s += __shfl_xor_sync(0xffffffffu, s, off);
        float inv = 1.0f / s;
        size_t base = (size_t)bh * 4096 + r * 64;
        g_at[base + lane]      = __float2half_rn(e0 * inv * rv_s[lane]);
        g_at[base + lane + 32] = __float2half_rn(e1 * inv * rv_s[lane + 32]);
    }
}

// ---------------- apply: fp16 HMMA out = attn @ v -> ao fp16 ----------------
#define AP_A 0
#define AP_V 8192
#define AP_SMEM 24576

__global__ __launch_bounds__(256) void apply_kernel() {
    extern __shared__ char smem[];
    uint32_t sb = smem_u32(smem);
    int ntile = blockIdx.x;
    int bh = blockIdx.y;
    int b = bh >> 3, hg = bh & 7;
    int tid = threadIdx.x, l = tid & 31, wid = tid >> 5;
    int wm = wid & 1, wn = wid >> 1;

#pragma unroll
    for (int it = 0; it < 2; it++) {
        int idx = tid + it * 256;
        int r = idx >> 3, c8 = idx & 7;
        uint32_t swo = sw128((uint32_t)(r * 128 + c8 * 16));
        CP16(sb + AP_A + swo, g_at + (size_t)bh * 4096 + r * 64 + c8 * 8);
    }
    const __half* vp = g_v + ((size_t)b * C_ + hg * HD) * NPIX + ntile * 128;
#pragma unroll
    for (int it = 0; it < 4; it++) {
        int idx = tid + it * 256;
        int r = idx >> 4;
        int n8 = idx & 15;
        int s = n8 >> 3, nl = n8 & 7;
        uint32_t swo = (uint32_t)(s * 8192) + sw128((uint32_t)(r * 128 + nl * 16));
        CP16(sb + AP_V + swo, vp + (size_t)r * NPIX + n8 * 8);
    }
    CP_COMMIT();
    CP_WAIT0();
    __syncthreads();

    float acc[2][4][4] = {};
    int lr = l & 15, lc = (l >> 4) << 4;
#pragma unroll
    for (int k16 = 0; k16 < 4; k16++) {
        uint32_t ah[2][4], bf[2][4];
#pragma unroll
        for (int mt = 0; mt < 2; mt++) {
            uint32_t swo = sw128((uint32_t)((wm * 32 + mt * 16 + lr) * 128 + k16 * 32 + lc));
            LDSM_X4(ah[mt], sb + AP_A + swo);
        }
        uint32_t pb = (uint32_t)((wn >> 1) * 8192);
#pragma unroll
        for (int h = 0; h < 2; h++) {
            uint32_t swo = sw128((uint32_t)((k16 * 16 + lr) * 128 + (wn & 1) * 64 + h * 32 + lc));
            LDSM_X4T(bf[h], sb + AP_V + pb + swo);
        }
#pragma unroll
        for (int mt = 0; mt < 2; mt++)
#pragma unroll
            for (int nt = 0; nt < 4; nt++) {
                int h = nt >> 1, pr = (nt & 1) * 2;
                MMA16816(acc[mt][nt], ah[mt], bf[h][pr], bf[h][pr + 1]);
            }
    }

    int l4 = l >> 2, l2 = (l & 3) << 1;
#pragma unroll
    for (int mt = 0; mt < 2; mt++)
#pragma unroll
        for (int half = 0; half < 2; half++) {
            int row = wm * 32 + mt * 16 + l4 + half * 8;
            __half* po = g_ao + ((size_t)b * C_ + hg * HD + row) * NPIX + ntile * 128;
#pragma unroll
            for (int nt = 0; nt < 4; nt++) {
                int col = wn * 32 + nt * 8 + l2;
                *(uint32_t*)(po + col) =
                    pack2h(__float2half_rn(acc[mt][nt][half * 2]),
                           __float2half_rn(acc[mt][nt][half * 2 + 1]));
            }
        }
}

// ---------------- launch ----------------
extern "C" void kernel_launch(void* const* d_in, const int* in_sizes, int n_in,
                              void* d_out, int out_size) {
    const float* x  = (const float*)d_in[0];
    const float* dw = (const float*)d_in[1];
    const float* qw = (const float*)d_in[2];
    const float* kw = (const float*)d_in[3];
    const float* vw = (const float*)d_in[4];
    const float* pw = (const float*)d_in[5];
    float* out = (float*)d_out;

    __half *yp, *aop, *whp, *wlp;
    cudaGetSymbolAddress((void**)&yp,  g_y);
    cudaGetSymbolAddress((void**)&aop, g_ao);
    cudaGetSymbolAddress((void**)&whp, g_wh);
    cudaGetSymbolAddress((void**)&wlp, g_wl);

    cudaFuncSetAttribute(gemm_hmma_kernel<1>, cudaFuncAttributeMaxDynamicSharedMemorySize, 98304);
    cudaFuncSetAttribute(gemm_hmma_kernel<2>, cudaFuncAttributeMaxDynamicSharedMemorySize, 98304);
    cudaFuncSetAttribute(scores_kernel, cudaFuncAttributeMaxDynamicSharedMemorySize, SC_SMEM);
    cudaFuncSetAttribute(apply_kernel, cudaFuncAttributeMaxDynamicSharedMemorySize, AP_SMEM);

    zero_kernel<<<16, 256>>>();                                        // 1
    dwconv_kernel<<<dim3(NPIX / 256, B_ * C_), 256>>>(x, dw);          // 2
    convert_w_kernel<<<4096, 256>>>(qw, kw, vw, pw);                   // 3
    // fused QKV GEMM, M=1536, 1-term fp16 (profiled slot)
    gemm_hmma_kernel<1><<<dim3(NPIX / 128, 24, B_), 256, 98304>>>(     // 4
        whp, wlp, yp, nullptr, 1);
    scores_kernel<<<dim3(8, B_ * HEADS_), 256, SC_SMEM>>>();           // 5
    softmax_kernel<<<B_ * HEADS_, 256>>>();                            // 6
    apply_kernel<<<dim3(NPIX / 128, B_ * HEADS_), 256, AP_SMEM>>>();   // 7
    // proj GEMM: 2-term for accuracy, weight rows [1536, 2048)
    gemm_hmma_kernel<2><<<dim3(NPIX / 128, 8, B_), 256, 98304>>>(      // 8
        whp + 1536 * C_, wlp + 1536 * C_, aop, out, 0);
}

// round 9
// speedup vs baseline: 5.5197x; 1.0508x over previous
#include <cuda_runtime.h>
#include <cuda_fp16.h>
#include <math.h>
#include <stdint.h>

#define B_     8
#define C_     512
#define HH     64
#define WW     64
#define NPIX   4096
#define HEADS_ 8
#define HD     64
#define TOFF   (B_ * C_ * NPIX)

// ---------------- scratch ----------------
__device__ __align__(16) __half g_y [TOFF];
__device__ __align__(16) __half g_q [TOFF], g_k[TOFF], g_v[TOFF];
__device__ __align__(16) __half g_ao[TOFF];
__device__ __align__(16) __half g_wh[4 * C_ * C_], g_wl[4 * C_ * C_];
__device__ __align__(16) __half g_at[B_ * HEADS_ * HD * HD];
__device__ float g_part[B_ * HEADS_ * 8 * HD * HD];
__device__ float g_sq[3 * B_ * C_];

// ---------------- PTX helpers (baseline sm_80+) ----------------
__device__ __forceinline__ uint32_t smem_u32(const void* p) {
    uint32_t a;
    asm("{ .reg .u64 t; cvta.to.shared.u64 t, %1; cvt.u32.u64 %0, t; }" : "=r"(a) : "l"(p));
    return a;
}
#define CP16(s, g) asm volatile("cp.async.cg.shared.global [%0], [%1], 16;" :: "r"(s), "l"(g))
#define CP_COMMIT() asm volatile("cp.async.commit_group;" ::: "memory")
#define CP_WAIT(n)  asm volatile("cp.async.wait_group %0;" :: "n"(n) : "memory")
#define CP_WAIT0()  asm volatile("cp.async.wait_group 0;" ::: "memory")

#define LDSM_X4(r, a) \
    asm volatile("ldmatrix.sync.aligned.m8n8.x4.shared.b16 {%0,%1,%2,%3}, [%4];" \
        : "=r"((r)[0]), "=r"((r)[1]), "=r"((r)[2]), "=r"((r)[3]) : "r"(a))
#define LDSM_X4T(r, a) \
    asm volatile("ldmatrix.sync.aligned.m8n8.x4.trans.shared.b16 {%0,%1,%2,%3}, [%4];" \
        : "=r"((r)[0]), "=r"((r)[1]), "=r"((r)[2]), "=r"((r)[3]) : "r"(a))
#define MMA16816(d, a, b0, b1) \
    asm volatile("mma.sync.aligned.m16n8k16.row.col.f32.f16.f16.f32 " \
        "{%0,%1,%2,%3}, {%4,%5,%6,%7}, {%8,%9}, {%0,%1,%2,%3};" \
        : "+f"((d)[0]), "+f"((d)[1]), "+f"((d)[2]), "+f"((d)[3]) \
        : "r"((a)[0]), "r"((a)[1]), "r"((a)[2]), "r"((a)[3]), "r"(b0), "r"(b1))

__device__ __forceinline__ uint32_t sw128(uint32_t o) { return o ^ ((o >> 3) & 0x70); }

__device__ __forceinline__ void split_h(float v, __half& hi, __half& lo) {
    hi = __float2half_rn(v);
    lo = __float2half_rn(v - __half2float(hi));
}
__device__ __forceinline__ uint32_t pack2h(__half a, __half b) {
    unsigned short ua = *(unsigned short*)&a, ub = *(unsigned short*)&b;
    return (uint32_t)ua | ((uint32_t)ub << 16);
}
__device__ __forceinline__ float inv_norm(float s) {
    return 1.0f / fmaxf(sqrtf(s), 1e-12f);
}

// ---------------- zero sumsq ----------------
__global__ __launch_bounds__(256) void zero_kernel() {
    for (int i = blockIdx.x * 256 + threadIdx.x; i < 3 * B_ * C_; i += gridDim.x * 256)
        g_sq[i] = 0.f;
}

// ---------------- depthwise 3x3 -> fp16 ----------------
__global__ __launch_bounds__(256) void dwconv_kernel(const float* __restrict__ x,
                                                     const float* __restrict__ w) {
    int plane = blockIdx.y;
    int c = plane & (C_ - 1);
    __shared__ float ws[9];
    if (threadIdx.x < 9) ws[threadIdx.x] = w[c * 9 + threadIdx.x];
    __syncthreads();
    int p = blockIdx.x * 256 + threadIdx.x;
    int h = p >> 6, wc = p & 63;
    const float* xp = x + (size_t)plane * NPIX;
    float acc = 0.f;
#pragma unroll
    for (int kh = 0; kh < 3; kh++) {
        int hh = h + kh - 1;
        if (hh < 0 || hh >= HH) continue;
#pragma unroll
        for (int kw = 0; kw < 3; kw++) {
            int wcol = wc + kw - 1;
            if (wcol < 0 || wcol >= WW) continue;
            acc = fmaf(ws[kh * 3 + kw], xp[hh * WW + wcol], acc);
        }
    }
    g_y[(size_t)plane * NPIX + p] = __float2half_rn(acc);
}

// ---------------- weight conversion ----------------
__global__ __launch_bounds__(256) void convert_w_kernel(const float* __restrict__ qw,
                                                        const float* __restrict__ kw,
                                                        const float* __restrict__ vw,
                                                        const float* __restrict__ pw) {
    int idx = blockIdx.x * 256 + threadIdx.x;
    int m = idx >> 18;
    const float* src = (m == 0) ? qw : (m == 1) ? kw : (m == 2) ? vw : pw;
    float v = src[idx & 262143];
    __half hi, lo;
    split_h(v, hi, lo);
    g_wh[idx] = hi;
    g_wl[idx] = lo;
}

// ---------------- QKV GEMM: 1-term fp16, CTA 128x128, 3-stage ----------------
#define Q_A 0
#define Q_B 16384
#define Q_STAGE 32768
#define Q_SMEM (3 * Q_STAGE)

__global__ __launch_bounds__(256, 2) void gemm_qkv_kernel(const __half* __restrict__ Wh,
                                                          const __half* __restrict__ Bg) {
    extern __shared__ char smem[];
    uint32_t sb = smem_u32(smem);
    int tid = threadIdx.x;
    int l = tid & 31, wid = tid >> 5;
    int wm = wid & 3, wn = wid >> 2;        // warp tile: 32 rows x 64 cols
    int bn = blockIdx.x * 128;
    int bm = blockIdx.y * 128;
    int bz = blockIdx.z;
    const __half* Bp = Bg + (size_t)bz * C_ * NPIX;

    auto load_chunk = [&](int chunk, int stg) {
        uint32_t st = sb + stg * Q_STAGE;
        int k0 = chunk * 64;
#pragma unroll
        for (int it = 0; it < 4; it++) {
            int idx = tid + it * 256;              // 0..1023
            int ar = idx >> 3;                     // 0..127
            int ac = (idx & 7) << 3;
            uint32_t aswo = sw128((uint32_t)(ar * 128 + ac * 2));
            CP16(st + Q_A + aswo, Wh + (size_t)(bm + ar) * C_ + k0 + ac);
            int brr = idx >> 4;                    // 0..63
            int bnn = (idx & 15) << 3;             // 0..120
            int s = bnn >> 6, nl = bnn & 63;
            uint32_t bswo = (uint32_t)(s * 8192) + sw128((uint32_t)(brr * 128 + nl * 2));
            CP16(st + Q_B + bswo, Bp + (size_t)(k0 + brr) * NPIX + bn + bnn);
        }
    };

    float acc[2][8][4] = {};
    int lr = l & 15;
    int lc = (l >> 4) << 4;

    load_chunk(0, 0); CP_COMMIT();
    load_chunk(1, 1); CP_COMMIT();

    for (int chunk = 0; chunk < 8; chunk++) {
        CP_WAIT(1);
        __syncthreads();
        uint32_t st = sb + (chunk % 3) * Q_STAGE;
#pragma unroll
        for (int k16 = 0; k16 < 4; k16++) {
            uint32_t ah[2][4], bf[4][4];
#pragma unroll
            for (int mt = 0; mt < 2; mt++) {
                uint32_t swo = sw128((uint32_t)((wm * 32 + mt * 16 + lr) * 128 + k16 * 32 + lc));
                LDSM_X4(ah[mt], st + Q_A + swo);
            }
            uint32_t pb = (uint32_t)(wn * 8192);
#pragma unroll
            for (int h = 0; h < 4; h++) {
                uint32_t swo = sw128((uint32_t)((k16 * 16 + lr) * 128 + h * 32 + lc));
                LDSM_X4T(bf[h], st + Q_B + pb + swo);
            }
#pragma unroll
            for (int mt = 0; mt < 2; mt++)
#pragma unroll
                for (int nt = 0; nt < 8; nt++) {
                    int h = nt >> 1, pr = (nt & 1) * 2;
                    MMA16816(acc[mt][nt], ah[mt], bf[h][pr], bf[h][pr + 1]);
                }
        }
        __syncthreads();
        if (chunk + 2 < 8) load_chunk(chunk + 2, (chunk + 2) % 3);
        CP_COMMIT();
    }

    // epilogue -> q/k/v fp16 + per-row sum of squares
    int l4 = l >> 2, l2 = (l & 3) << 1;
#pragma unroll
    for (int mt = 0; mt < 2; mt++) {
#pragma unroll
        for (int half = 0; half < 2; half++) {
            int row = bm + wm * 32 + mt * 16 + l4 + half * 8;
            int which = row >> 9, ml = row & 511;
            __half* pq = ((which == 0) ? g_q : (which == 1) ? g_k : g_v)
                         + ((size_t)bz * C_ + ml) * NPIX;
            float ss = 0.f;
#pragma unroll
            for (int nt = 0; nt < 8; nt++) {
                int col = bn + wn * 64 + nt * 8 + l2;
                float v0 = acc[mt][nt][half * 2], v1 = acc[mt][nt][half * 2 + 1];
                ss += v0 * v0 + v1 * v1;
                *(uint32_t*)(pq + col) = pack2h(__float2half_rn(v0), __float2half_rn(v1));
            }
            ss += __shfl_xor_sync(0xffffffffu, ss, 1);
            ss += __shfl_xor_sync(0xffffffffu, ss, 2);
            if ((l & 3) == 0)
                atomicAdd(&g_sq[which * (B_ * C_) + bz * C_ + ml], ss);
        }
    }
}

// ---------------- proj GEMM: 2-term fp16, CTA 64x128, 3-stage ----------------
#define P_AHI 0
#define P_ALO 8192
#define P_B   16384
#define P_STAGE 32768
#define P_SMEM (3 * P_STAGE)

__global__ __launch_bounds__(256, 2) void gemm_proj_kernel(const __half* __restrict__ Wh,
                                                           const __half* __restrict__ Wl,
                                                           const __half* __restrict__ Bg,
                                                           float* __restrict__ Cout) {
    extern __shared__ char smem[];
    uint32_t sb = smem_u32(smem);
    int tid = threadIdx.x;
    int l = tid & 31, wid = tid >> 5;
    int wm = wid & 1, wn = wid >> 1;        // warp tile: 32 rows x 32 cols
    int bn = blockIdx.x * 128;
    int bm = blockIdx.y * 64;
    int bz = blockIdx.z;
    const __half* Bp = Bg + (size_t)bz * C_ * NPIX;

    auto load_chunk = [&](int chunk, int stg) {
        uint32_t st = sb + stg * P_STAGE;
        int k0 = chunk * 64;
#pragma unroll
        for (int it = 0; it < 2; it++) {
            int idx = tid + it * 256;
            int ar = idx >> 3;
            int ac = (idx & 7) << 3;
            uint32_t aswo = sw128((uint32_t)(ar * 128 + ac * 2));
            CP16(st + P_AHI + aswo, Wh + (size_t)(bm + ar) * C_ + k0 + ac);
            CP16(st + P_ALO + aswo, Wl + (size_t)(bm + ar) * C_ + k0 + ac);
        }
#pragma unroll
        for (int it = 0; it < 4; it++) {
            int idx = tid + it * 256;
            int brr = idx >> 4;
            int bnn = (idx & 15) << 3;
            int s = bnn >> 6, nl = bnn & 63;
            uint32_t bswo = (uint32_t)(s * 8192) + sw128((uint32_t)(brr * 128 + nl * 2));
            CP16(st + P_B + bswo, Bp + (size_t)(k0 + brr) * NPIX + bn + bnn);
        }
    };

    float acc[2][4][4] = {};
    int lr = l & 15;
    int lc = (l >> 4) << 4;

    load_chunk(0, 0); CP_COMMIT();
    load_chunk(1, 1); CP_COMMIT();

    for (int chunk = 0; chunk < 8; chunk++) {
        CP_WAIT(1);
        __syncthreads();
        uint32_t st = sb + (chunk % 3) * P_STAGE;
#pragma unroll
        for (int k16 = 0; k16 < 4; k16++) {
            uint32_t ah[2][4], al[2][4], bf[2][4];
            int kb = k16 * 32 + lc;
#pragma unroll
            for (int mt = 0; mt < 2; mt++) {
                uint32_t swo = sw128((uint32_t)((wm * 32 + mt * 16 + lr) * 128 + kb));
                LDSM_X4(ah[mt], st + P_AHI + swo);
                LDSM_X4(al[mt], st + P_ALO + swo);
            }
            uint32_t pb = (uint32_t)((wn >> 1) * 8192);
#pragma unroll
            for (int h = 0; h < 2; h++) {
                uint32_t swo = sw128((uint32_t)((k16 * 16 + lr) * 128 + (wn & 1) * 64 + h * 32 + lc));
                LDSM_X4T(bf[h], st + P_B + pb + swo);
            }
#pragma unroll
            for (int mt = 0; mt < 2; mt++)
#pragma unroll
                for (int nt = 0; nt < 4; nt++) {
                    int h = nt >> 1, pr = (nt & 1) * 2;
                    MMA16816(acc[mt][nt], ah[mt], bf[h][pr], bf[h][pr + 1]);
                    MMA16816(acc[mt][nt], al[mt], bf[h][pr], bf[h][pr + 1]);
                }
        }
        __syncthreads();
        if (chunk + 2 < 8) load_chunk(chunk + 2, (chunk + 2) % 3);
        CP_COMMIT();
    }

    int l4 = l >> 2, l2 = (l & 3) << 1;
#pragma unroll
    for (int mt = 0; mt < 2; mt++)
#pragma unroll
        for (int half = 0; half < 2; half++) {
            int row = bm + wm * 32 + mt * 16 + l4 + half * 8;
            float* base = Cout + ((size_t)bz * C_ + row) * NPIX;
#pragma unroll
            for (int nt = 0; nt < 4; nt++) {
                int col = bn + wn * 32 + nt * 8 + l2;
                *(float2*)(base + col) =
                    make_float2(acc[mt][nt][half * 2], acc[mt][nt][half * 2 + 1]);
            }
        }
}

// ---------------- scores: fp16 HMMA, split-K partials ----------------
#define SC_Q 0
#define SC_K 8192
#define SC_STAGE 16384
#define SC_SMEM (2 * SC_STAGE)

__global__ __launch_bounds__(256) void scores_kernel() {
    extern __shared__ char smem[];
    uint32_t sb = smem_u32(smem);
    int sp = blockIdx.x, bh = blockIdx.y;
    int b = bh >> 3, hg = bh & 7;
    int tid = threadIdx.x, l = tid & 31, wid = tid >> 5;
    int wm = wid & 1, wn = wid >> 1;
    const __half* qp = g_q + ((size_t)b * C_ + hg * HD) * NPIX;
    const __half* kp = g_k + ((size_t)b * C_ + hg * HD) * NPIX;
    int px0 = sp * 512;

    auto load_chunk = [&](int chunk, int stg) {
        uint32_t st = sb + stg * SC_STAGE;
        int k0 = px0 + chunk * 64;
#pragma unroll
        for (int it = 0; it < 2; it++) {
            int idx = tid + it * 256;
            int r = idx >> 3;
            int c8 = idx & 7;
            uint32_t swo = sw128((uint32_t)(r * 128 + c8 * 16));
            size_t go = (size_t)r * NPIX + k0 + c8 * 8;
            CP16(st + SC_Q + swo, qp + go);
            CP16(st + SC_K + swo, kp + go);
        }
    };

    float acc[2][2][4] = {};
    int lr = l & 15, lc = (l >> 4) << 4;
    int bn_row = wn * 16 + (l & 7) + ((l >> 4) << 3);
    int bn_kb = ((l >> 3) & 1) * 16;

    load_chunk(0, 0); CP_COMMIT();
    load_chunk(1, 1); CP_COMMIT();

    for (int chunk = 0; chunk < 8; chunk++) {
        CP_WAIT(1);
        __syncthreads();
        uint32_t st = sb + (chunk & 1) * SC_STAGE;
#pragma unroll
        for (int k16 = 0; k16 < 4; k16++) {
            uint32_t ah[2][4], bf[4];
#pragma unroll
            for (int mt = 0; mt < 2; mt++) {
                uint32_t swo = sw128((uint32_t)((wm * 32 + mt * 16 + lr) * 128 + k16 * 32 + lc));
                LDSM_X4(ah[mt], st + SC_Q + swo);
            }
            uint32_t swb = sw128((uint32_t)(bn_row * 128 + k16 * 32 + bn_kb));
            LDSM_X4(bf, st + SC_K + swb);
#pragma unroll
            for (int mt = 0; mt < 2; mt++)
#pragma unroll
                for (int nt = 0; nt < 2; nt++)
                    MMA16816(acc[mt][nt], ah[mt], bf[nt * 2], bf[nt * 2 + 1]);
        }
        __syncthreads();
        if (chunk + 2 < 8) load_chunk(chunk + 2, chunk & 1);
        CP_COMMIT();
    }

    float* op = g_part + ((size_t)bh * 8 + sp) * 4096;
    int l4 = l >> 2, l2 = (l & 3) << 1;
#pragma unroll
    for (int mt = 0; mt < 2; mt++)
#pragma unroll
        for (int half = 0; half < 2; half++) {
            int row = wm * 32 + mt * 16 + l4 + half * 8;
#pragma unroll
            for (int nt = 0; nt < 2; nt++) {
                int col = wn * 16 + nt * 8 + l2;
                *(float2*)(op + row * 64 + col) =
                    make_float2(acc[mt][nt][half * 2], acc[mt][nt][half * 2 + 1]);
            }
        }
}

// ---------------- reduce + softmax, fold norms, -> attn fp16 ----------------
__global__ __launch_bounds__(256) void softmax_kernel() {
    int bh = blockIdx.x;
    int b = bh >> 3, hg = bh & 7;
    int cb = b * C_ + hg * HD;
    __shared__ float Ss[64][64];
    __shared__ float rv_s[64];
    int tid = threadIdx.x;
    const float scale = 0.125f;
    if (tid < 64) rv_s[tid] = inv_norm(g_sq[2 * B_ * C_ + cb + tid]);
    for (int i = tid; i < 4096; i += 256) {
        float s = 0.f;
#pragma unroll
        for (int p = 0; p < 8; p++) s += g_part[((size_t)bh * 8 + p) * 4096 + i];
        int r = i >> 6, c = i & 63;
        Ss[r][c] = s * inv_norm(g_sq[cb + r]) * scale * inv_norm(g_sq[B_ * C_ + cb + c]);
    }
    __syncthreads();
    int warp = tid >> 5, lane = tid & 31;
#pragma unroll
    for (int rr = 0; rr < 8; rr++) {
        int r = warp * 8 + rr;
        float v0 = Ss[r][lane], v1 = Ss[r][lane + 32];
        float m = fmaxf(v0, v1);
#pragma unroll
        for (int off = 16; off; off >>= 1) m = fmaxf(m, __shfl_xor_sync(0xffffffffu, m, off));
        float e0 = __expf(v0 - m), e1 = __expf(v1 - m);
        float s = e0 + e1;
#pragma unroll
        for (int off = 16; off; off >>= 1) s += __shfl_xor_sync(0xffffffffu, s, off);
        float inv = 1.0f / s;
        size_t base = (size_t)bh * 4096 + r * 64;
        g_at[base + lane]      = __float2half_rn(e0 * inv * rv_s[lane]);
        g_at[base + lane + 32] = __float2half_rn(e1 * inv * rv_s[lane + 32]);
    }
}

// ---------------- apply: fp16 HMMA out = attn @ v -> ao fp16 ----------------
#define AP_A 0
#define AP_V 8192
#define AP_SMEM 24576

__global__ __launch_bounds__(256) void apply_kernel() {
    extern __shared__ char smem[];
    uint32_t sb = smem_u32(smem);
    int ntile = blockIdx.x;
    int bh = blockIdx.y;
    int b = bh >> 3, hg = bh & 7;
    int tid = threadIdx.x, l = tid & 31, wid = tid >> 5;
    int wm = wid & 1, wn = wid >> 1;

#pragma unroll
    for (int it = 0; it < 2; it++) {
        int idx = tid + it * 256;
        int r = idx >> 3, c8 = idx & 7;
        uint32_t swo = sw128((uint32_t)(r * 128 + c8 * 16));
        CP16(sb + AP_A + swo, g_at + (size_t)bh * 4096 + r * 64 + c8 * 8);
    }
    const __half* vp = g_v + ((size_t)b * C_ + hg * HD) * NPIX + ntile * 128;
#pragma unroll
    for (int it = 0; it < 4; it++) {
        int idx = tid + it * 256;
        int r = idx >> 4;
        int n8 = idx & 15;
        int s = n8 >> 3, nl = n8 & 7;
        uint32_t swo = (uint32_t)(s * 8192) + sw128((uint32_t)(r * 128 + nl * 16));
        CP16(sb + AP_V + swo, vp + (size_t)r * NPIX + n8 * 8);
    }
    CP_COMMIT();
    CP_WAIT0();
    __syncthreads();

    float acc[2][4][4] = {};
    int lr = l & 15, lc = (l >> 4) << 4;
#pragma unroll
    for (int k16 = 0; k16 < 4; k16++) {
        uint32_t ah[2][4], bf[2][4];
#pragma unroll
        for (int mt = 0; mt < 2; mt++) {
            uint32_t swo = sw128((uint32_t)((wm * 32 + mt * 16 + lr) * 128 + k16 * 32 + lc));
            LDSM_X4(ah[mt], sb + AP_A + swo);
        }
        uint32_t pb = (uint32_t)((wn >> 1) * 8192);
#pragma unroll
        for (int h = 0; h < 2; h++) {
            uint32_t swo = sw128((uint32_t)((k16 * 16 + lr) * 128 + (wn & 1) * 64 + h * 32 + lc));
            LDSM_X4T(bf[h], sb + AP_V + pb + swo);
        }
#pragma unroll
        for (int mt = 0; mt < 2; mt++)
#pragma unroll
            for (int nt = 0; nt < 4; nt++) {
                int h = nt >> 1, pr = (nt & 1) * 2;
                MMA16816(acc[mt][nt], ah[mt], bf[h][pr], bf[h][pr + 1]);
            }
    }

    int l4 = l >> 2, l2 = (l & 3) << 1;
#pragma unroll
    for (int mt = 0; mt < 2; mt++)
#pragma unroll
        for (int half = 0; half < 2; half++) {
            int row = wm * 32 + mt * 16 + l4 + half * 8;
            __half* po = g_ao + ((size_t)b * C_ + hg * HD + row) * NPIX + ntile * 128;
#pragma unroll
            for (int nt = 0; nt < 4; nt++) {
                int col = wn * 32 + nt * 8 + l2;
                *(uint32_t*)(po + col) =
                    pack2h(__float2half_rn(acc[mt][nt][half * 2]),
                           __float2half_rn(acc[mt][nt][half * 2 + 1]));
            }
        }
}

// ---------------- launch ----------------
extern "C" void kernel_launch(void* const* d_in, const int* in_sizes, int n_in,
                              void* d_out, int out_size) {
    const float* x  = (const float*)d_in[0];
    const float* dw = (const float*)d_in[1];
    const float* qw = (const float*)d_in[2];
    const float* kw = (const float*)d_in[3];
    const float* vw = (const float*)d_in[4];
    const float* pw = (const float*)d_in[5];
    float* out = (float*)d_out;

    __half *yp, *aop, *whp, *wlp;
    cudaGetSymbolAddress((void**)&yp,  g_y);
    cudaGetSymbolAddress((void**)&aop, g_ao);
    cudaGetSymbolAddress((void**)&whp, g_wh);
    cudaGetSymbolAddress((void**)&wlp, g_wl);

    cudaFuncSetAttribute(gemm_qkv_kernel,  cudaFuncAttributeMaxDynamicSharedMemorySize, Q_SMEM);
    cudaFuncSetAttribute(gemm_proj_kernel, cudaFuncAttributeMaxDynamicSharedMemorySize, P_SMEM);
    cudaFuncSetAttribute(scores_kernel, cudaFuncAttributeMaxDynamicSharedMemorySize, SC_SMEM);
    cudaFuncSetAttribute(apply_kernel,  cudaFuncAttributeMaxDynamicSharedMemorySize, AP_SMEM);

    zero_kernel<<<16, 256>>>();                                        // 1
    dwconv_kernel<<<dim3(NPIX / 256, B_ * C_), 256>>>(x, dw);          // 2
    convert_w_kernel<<<4096, 256>>>(qw, kw, vw, pw);                   // 3
    // fused QKV GEMM, M=1536, CTA 128x128, 1-term (profiled slot)
    gemm_qkv_kernel<<<dim3(NPIX / 128, 12, B_), 256, Q_SMEM>>>(whp, yp); // 4
    scores_kernel<<<dim3(8, B_ * HEADS_), 256, SC_SMEM>>>();           // 5
    softmax_kernel<<<B_ * HEADS_, 256>>>();                            // 6
    apply_kernel<<<dim3(NPIX / 128, B_ * HEADS_), 256, AP_SMEM>>>();   // 7
    // proj GEMM: 2-term, weight rows [1536, 2048)
    gemm_proj_kernel<<<dim3(NPIX / 128, 8, B_), 256, P_SMEM>>>(        // 8
        whp + 1536 * C_, wlp + 1536 * C_, aop, out);
}

// round 10
// speedup vs baseline: 5.9657x; 1.0808x over previous
#include <cuda_runtime.h>
#include <cuda_fp16.h>
#include <math.h>
#include <stdint.h>

#define B_     8
#define C_     512
#define HH     64
#define WW     64
#define NPIX   4096
#define HEADS_ 8
#define HD     64
#define TOFF   (B_ * C_ * NPIX)

// ---------------- scratch ----------------
__device__ __align__(16) __half g_y [TOFF];
__device__ __align__(16) __half g_q [TOFF], g_k[TOFF], g_v[TOFF];
__device__ __align__(16) __half g_ao[TOFF];
__device__ __align__(16) __half g_wh[4 * C_ * C_];
__device__ __align__(16) __half g_at[B_ * HEADS_ * HD * HD];
__device__ float g_part[B_ * HEADS_ * 8 * HD * HD];
__device__ float g_sq[3 * B_ * C_];

// ---------------- PTX helpers (baseline sm_80+) ----------------
__device__ __forceinline__ uint32_t smem_u32(const void* p) {
    uint32_t a;
    asm("{ .reg .u64 t; cvta.to.shared.u64 t, %1; cvt.u32.u64 %0, t; }" : "=r"(a) : "l"(p));
    return a;
}
#define CP16(s, g) asm volatile("cp.async.cg.shared.global [%0], [%1], 16;" :: "r"(s), "l"(g))
#define CP_COMMIT() asm volatile("cp.async.commit_group;" ::: "memory")
#define CP_WAIT(n)  asm volatile("cp.async.wait_group %0;" :: "n"(n) : "memory")
#define CP_WAIT0()  asm volatile("cp.async.wait_group 0;" ::: "memory")

#define LDSM_X4(r, a) \
    asm volatile("ldmatrix.sync.aligned.m8n8.x4.shared.b16 {%0,%1,%2,%3}, [%4];" \
        : "=r"((r)[0]), "=r"((r)[1]), "=r"((r)[2]), "=r"((r)[3]) : "r"(a))
#define LDSM_X4T(r, a) \
    asm volatile("ldmatrix.sync.aligned.m8n8.x4.trans.shared.b16 {%0,%1,%2,%3}, [%4];" \
        : "=r"((r)[0]), "=r"((r)[1]), "=r"((r)[2]), "=r"((r)[3]) : "r"(a))
#define MMA16816(d, a, b0, b1) \
    asm volatile("mma.sync.aligned.m16n8k16.row.col.f32.f16.f16.f32 " \
        "{%0,%1,%2,%3}, {%4,%5,%6,%7}, {%8,%9}, {%0,%1,%2,%3};" \
        : "+f"((d)[0]), "+f"((d)[1]), "+f"((d)[2]), "+f"((d)[3]) \
        : "r"((a)[0]), "r"((a)[1]), "r"((a)[2]), "r"((a)[3]), "r"(b0), "r"(b1))

__device__ __forceinline__ uint32_t sw128(uint32_t o) { return o ^ ((o >> 3) & 0x70); }

__device__ __forceinline__ uint32_t pack2h(__half a, __half b) {
    unsigned short ua = *(unsigned short*)&a, ub = *(unsigned short*)&b;
    return (uint32_t)ua | ((uint32_t)ub << 16);
}
__device__ __forceinline__ float inv_norm(float s) {
    return 1.0f / fmaxf(sqrtf(s), 1e-12f);
}

// ---------------- zero sumsq ----------------
__global__ __launch_bounds__(256) void zero_kernel() {
    for (int i = blockIdx.x * 256 + threadIdx.x; i < 3 * B_ * C_; i += gridDim.x * 256)
        g_sq[i] = 0.f;
}

// ---------------- depthwise 3x3 -> fp16 ----------------
__global__ __launch_bounds__(256) void dwconv_kernel(const float* __restrict__ x,
                                                     const float* __restrict__ w) {
    int plane = blockIdx.y;
    int c = plane & (C_ - 1);
    __shared__ float ws[9];
    if (threadIdx.x < 9) ws[threadIdx.x] = w[c * 9 + threadIdx.x];
    __syncthreads();
    int p = blockIdx.x * 256 + threadIdx.x;
    int h = p >> 6, wc = p & 63;
    const float* xp = x + (size_t)plane * NPIX;
    float acc = 0.f;
#pragma unroll
    for (int kh = 0; kh < 3; kh++) {
        int hh = h + kh - 1;
        if (hh < 0 || hh >= HH) continue;
#pragma unroll
        for (int kw = 0; kw < 3; kw++) {
            int wcol = wc + kw - 1;
            if (wcol < 0 || wcol >= WW) continue;
            acc = fmaf(ws[kh * 3 + kw], xp[hh * WW + wcol], acc);
        }
    }
    g_y[(size_t)plane * NPIX + p] = __float2half_rn(acc);
}

// ---------------- weight conversion: stacked [q;k;v;proj] -> fp16 ----------------
__global__ __launch_bounds__(256) void convert_w_kernel(const float* __restrict__ qw,
                                                        const float* __restrict__ kw,
                                                        const float* __restrict__ vw,
                                                        const float* __restrict__ pw) {
    int idx = blockIdx.x * 256 + threadIdx.x;
    int m = idx >> 18;
    const float* src = (m == 0) ? qw : (m == 1) ? kw : (m == 2) ? vw : pw;
    g_wh[idx] = __float2half_rn(src[idx & 262143]);
}

// ---------------- 1-term fp16 GEMM, CTA 128x128, 3-stage ----------------
// OUTMODE 0: write q/k/v fp16 + per-row sumsq. OUTMODE 1: write fp32 Cout.
#define Q_A 0
#define Q_B 16384
#define Q_STAGE 32768
#define Q_SMEM (3 * Q_STAGE)

template <int OUTMODE>
__global__ __launch_bounds__(256, 2) void gemm1_kernel(const __half* __restrict__ Wh,
                                                       const __half* __restrict__ Bg,
                                                       float* __restrict__ Cout) {
    extern __shared__ char smem[];
    uint32_t sb = smem_u32(smem);
    int tid = threadIdx.x;
    int l = tid & 31, wid = tid >> 5;
    int wm = wid & 3, wn = wid >> 2;        // warp tile: 32 rows x 64 cols
    int bn = blockIdx.x * 128;
    int bm = blockIdx.y * 128;
    int bz = blockIdx.z;
    const __half* Bp = Bg + (size_t)bz * C_ * NPIX;

    auto load_chunk = [&](int chunk, int stg) {
        uint32_t st = sb + stg * Q_STAGE;
        int k0 = chunk * 64;
#pragma unroll
        for (int it = 0; it < 4; it++) {
            int idx = tid + it * 256;              // 0..1023
            int ar = idx >> 3;                     // 0..127
            int ac = (idx & 7) << 3;
            uint32_t aswo = sw128((uint32_t)(ar * 128 + ac * 2));
            CP16(st + Q_A + aswo, Wh + (size_t)(bm + ar) * C_ + k0 + ac);
            int brr = idx >> 4;                    // 0..63
            int bnn = (idx & 15) << 3;             // 0..120
            int s = bnn >> 6, nl = bnn & 63;
            uint32_t bswo = (uint32_t)(s * 8192) + sw128((uint32_t)(brr * 128 + nl * 2));
            CP16(st + Q_B + bswo, Bp + (size_t)(k0 + brr) * NPIX + bn + bnn);
        }
    };

    float acc[2][8][4] = {};
    int lr = l & 15;
    int lc = (l >> 4) << 4;

    load_chunk(0, 0); CP_COMMIT();
    load_chunk(1, 1); CP_COMMIT();

    for (int chunk = 0; chunk < 8; chunk++) {
        CP_WAIT(1);
        __syncthreads();
        uint32_t st = sb + (chunk % 3) * Q_STAGE;
#pragma unroll
        for (int k16 = 0; k16 < 4; k16++) {
            uint32_t ah[2][4], bf[4][4];
#pragma unroll
            for (int mt = 0; mt < 2; mt++) {
                uint32_t swo = sw128((uint32_t)((wm * 32 + mt * 16 + lr) * 128 + k16 * 32 + lc));
                LDSM_X4(ah[mt], st + Q_A + swo);
            }
            uint32_t pb = (uint32_t)(wn * 8192);
#pragma unroll
            for (int h = 0; h < 4; h++) {
                uint32_t swo = sw128((uint32_t)((k16 * 16 + lr) * 128 + h * 32 + lc));
                LDSM_X4T(bf[h], st + Q_B + pb + swo);
            }
#pragma unroll
            for (int mt = 0; mt < 2; mt++)
#pragma unroll
                for (int nt = 0; nt < 8; nt++) {
                    int h = nt >> 1, pr = (nt & 1) * 2;
                    MMA16816(acc[mt][nt], ah[mt], bf[h][pr], bf[h][pr + 1]);
                }
        }
        __syncthreads();
        if (chunk + 2 < 8) load_chunk(chunk + 2, (chunk + 2) % 3);
        CP_COMMIT();
    }

    int l4 = l >> 2, l2 = (l & 3) << 1;
    if (OUTMODE == 0) {
#pragma unroll
        for (int mt = 0; mt < 2; mt++) {
#pragma unroll
            for (int half = 0; half < 2; half++) {
                int row = bm + wm * 32 + mt * 16 + l4 + half * 8;
                int which = row >> 9, ml = row & 511;
                __half* pq = ((which == 0) ? g_q : (which == 1) ? g_k : g_v)
                             + ((size_t)bz * C_ + ml) * NPIX;
                float ss = 0.f;
#pragma unroll
                for (int nt = 0; nt < 8; nt++) {
                    int col = bn + wn * 64 + nt * 8 + l2;
                    float v0 = acc[mt][nt][half * 2], v1 = acc[mt][nt][half * 2 + 1];
                    ss += v0 * v0 + v1 * v1;
                    *(uint32_t*)(pq + col) = pack2h(__float2half_rn(v0), __float2half_rn(v1));
                }
                ss += __shfl_xor_sync(0xffffffffu, ss, 1);
                ss += __shfl_xor_sync(0xffffffffu, ss, 2);
                if ((l & 3) == 0)
                    atomicAdd(&g_sq[which * (B_ * C_) + bz * C_ + ml], ss);
            }
        }
    } else {
#pragma unroll
        for (int mt = 0; mt < 2; mt++) {
#pragma unroll
            for (int half = 0; half < 2; half++) {
                int row = bm + wm * 32 + mt * 16 + l4 + half * 8;
                float* base = Cout + ((size_t)bz * C_ + row) * NPIX;
#pragma unroll
                for (int nt = 0; nt < 8; nt++) {
                    int col = bn + wn * 64 + nt * 8 + l2;
                    *(float2*)(base + col) =
                        make_float2(acc[mt][nt][half * 2], acc[mt][nt][half * 2 + 1]);
                }
            }
        }
    }
}

// ---------------- scores: fp16 HMMA, split-K partials ----------------
#define SC_Q 0
#define SC_K 8192
#define SC_STAGE 16384
#define SC_SMEM (2 * SC_STAGE)

__global__ __launch_bounds__(256) void scores_kernel() {
    extern __shared__ char smem[];
    uint32_t sb = smem_u32(smem);
    int sp = blockIdx.x, bh = blockIdx.y;
    int b = bh >> 3, hg = bh & 7;
    int tid = threadIdx.x, l = tid & 31, wid = tid >> 5;
    int wm = wid & 1, wn = wid >> 1;
    const __half* qp = g_q + ((size_t)b * C_ + hg * HD) * NPIX;
    const __half* kp = g_k + ((size_t)b * C_ + hg * HD) * NPIX;
    int px0 = sp * 512;

    auto load_chunk = [&](int chunk, int stg) {
        uint32_t st = sb + stg * SC_STAGE;
        int k0 = px0 + chunk * 64;
#pragma unroll
        for (int it = 0; it < 2; it++) {
            int idx = tid + it * 256;
            int r = idx >> 3;
            int c8 = idx & 7;
            uint32_t swo = sw128((uint32_t)(r * 128 + c8 * 16));
            size_t go = (size_t)r * NPIX + k0 + c8 * 8;
            CP16(st + SC_Q + swo, qp + go);
            CP16(st + SC_K + swo, kp + go);
        }
    };

    float acc[2][2][4] = {};
    int lr = l & 15, lc = (l >> 4) << 4;
    int bn_row = wn * 16 + (l & 7) + ((l >> 4) << 3);
    int bn_kb = ((l >> 3) & 1) * 16;

    load_chunk(0, 0); CP_COMMIT();
    load_chunk(1, 1); CP_COMMIT();

    for (int chunk = 0; chunk < 8; chunk++) {
        CP_WAIT(1);
        __syncthreads();
        uint32_t st = sb + (chunk & 1) * SC_STAGE;
#pragma unroll
        for (int k16 = 0; k16 < 4; k16++) {
            uint32_t ah[2][4], bf[4];
#pragma unroll
            for (int mt = 0; mt < 2; mt++) {
                uint32_t swo = sw128((uint32_t)((wm * 32 + mt * 16 + lr) * 128 + k16 * 32 + lc));
                LDSM_X4(ah[mt], st + SC_Q + swo);
            }
            uint32_t swb = sw128((uint32_t)(bn_row * 128 + k16 * 32 + bn_kb));
            LDSM_X4(bf, st + SC_K + swb);
#pragma unroll
            for (int mt = 0; mt < 2; mt++)
#pragma unroll
                for (int nt = 0; nt < 2; nt++)
                    MMA16816(acc[mt][nt], ah[mt], bf[nt * 2], bf[nt * 2 + 1]);
        }
        __syncthreads();
        if (chunk + 2 < 8) load_chunk(chunk + 2, chunk & 1);
        CP_COMMIT();
    }

    float* op = g_part + ((size_t)bh * 8 + sp) * 4096;
    int l4 = l >> 2, l2 = (l & 3) << 1;
#pragma unroll
    for (int mt = 0; mt < 2; mt++)
#pragma unroll
        for (int half = 0; half < 2; half++) {
            int row = wm * 32 + mt * 16 + l4 + half * 8;
#pragma unroll
            for (int nt = 0; nt < 2; nt++) {
                int col = wn * 16 + nt * 8 + l2;
                *(float2*)(op + row * 64 + col) =
                    make_float2(acc[mt][nt][half * 2], acc[mt][nt][half * 2 + 1]);
            }
        }
}

// ---------------- reduce + softmax, fold norms, -> attn fp16 ----------------
__global__ __launch_bounds__(256) void softmax_kernel() {
    int bh = blockIdx.x;
    int b = bh >> 3, hg = bh & 7;
    int cb = b * C_ + hg * HD;
    __shared__ float Ss[64][64];
    __shared__ float rv_s[64];
    int tid = threadIdx.x;
    const float scale = 0.125f;
    if (tid < 64) rv_s[tid] = inv_norm(g_sq[2 * B_ * C_ + cb + tid]);
    for (int i = tid; i < 4096; i += 256) {
        float s = 0.f;
#pragma unroll
        for (int p = 0; p < 8; p++) s += g_part[((size_t)bh * 8 + p) * 4096 + i];
        int r = i >> 6, c = i & 63;
        Ss[r][c] = s * inv_norm(g_sq[cb + r]) * scale * inv_norm(g_sq[B_ * C_ + cb + c]);
    }
    __syncthreads();
    int warp = tid >> 5, lane = tid & 31;
#pragma unroll
    for (int rr = 0; rr < 8; rr++) {
        int r = warp * 8 + rr;
        float v0 = Ss[r][lane], v1 = Ss[r][lane + 32];
        float m = fmaxf(v0, v1);
#pragma unroll
        for (int off = 16; off; off >>= 1) m = fmaxf(m, __shfl_xor_sync(0xffffffffu, m, off));
        float e0 = __expf(v0 - m), e1 = __expf(v1 - m);
        float s = e0 + e1;
#pragma unroll
        for (int off = 16; off; off >>= 1) s += __shfl_xor_sync(0xffffffffu, s, off);
        float inv = 1.0f / s;
        size_t base = (size_t)bh * 4096 + r * 64;
        g_at[base + lane]      = __float2half_rn(e0 * inv * rv_s[lane]);
        g_at[base + lane + 32] = __float2half_rn(e1 * inv * rv_s[lane + 32]);
    }
}

// ---------------- apply: fp16 HMMA out = attn @ v -> ao fp16 ----------------
#define AP_A 0
#define AP_V 8192
#define AP_SMEM 24576

__global__ __launch_bounds__(256) void apply_kernel() {
    extern __shared__ char smem[];
    uint32_t sb = smem_u32(smem);
    int ntile = blockIdx.x;
    int bh = blockIdx.y;
    int b = bh >> 3, hg = bh & 7;
    int tid = threadIdx.x, l = tid & 31, wid = tid >> 5;
    int wm = wid & 1, wn = wid >> 1;

#pragma unroll
    for (int it = 0; it < 2; it++) {
        int idx = tid + it * 256;
        int r = idx >> 3, c8 = idx & 7;
        uint32_t swo = sw128((uint32_t)(r * 128 + c8 * 16));
        CP16(sb + AP_A + swo, g_at + (size_t)bh * 4096 + r * 64 + c8 * 8);
    }
    const __half* vp = g_v + ((size_t)b * C_ + hg * HD) * NPIX + ntile * 128;
#pragma unroll
    for (int it = 0; it < 4; it++) {
        int idx = tid + it * 256;
        int r = idx >> 4;
        int n8 = idx & 15;
        int s = n8 >> 3, nl = n8 & 7;
        uint32_t swo = (uint32_t)(s * 8192) + sw128((uint32_t)(r * 128 + nl * 16));
        CP16(sb + AP_V + swo, vp + (size_t)r * NPIX + n8 * 8);
    }
    CP_COMMIT();
    CP_WAIT0();
    __syncthreads();

    float acc[2][4][4] = {};
    int lr = l & 15, lc = (l >> 4) << 4;
#pragma unroll
    for (int k16 = 0; k16 < 4; k16++) {
        uint32_t ah[2][4], bf[2][4];
#pragma unroll
        for (int mt = 0; mt < 2; mt++) {
            uint32_t swo = sw128((uint32_t)((wm * 32 + mt * 16 + lr) * 128 + k16 * 32 + lc));
            LDSM_X4(ah[mt], sb + AP_A + swo);
        }
        uint32_t pb = (uint32_t)((wn >> 1) * 8192);
#pragma unroll
        for (int h = 0; h < 2; h++) {
            uint32_t swo = sw128((uint32_t)((k16 * 16 + lr) * 128 + (wn & 1) * 64 + h * 32 + lc));
            LDSM_X4T(bf[h], sb + AP_V + pb + swo);
        }
#pragma unroll
        for (int mt = 0; mt < 2; mt++)
#pragma unroll
            for (int nt = 0; nt < 4; nt++) {
                int h = nt >> 1, pr = (nt & 1) * 2;
                MMA16816(acc[mt][nt], ah[mt], bf[h][pr], bf[h][pr + 1]);
            }
    }

    int l4 = l >> 2, l2 = (l & 3) << 1;
#pragma unroll
    for (int mt = 0; mt < 2; mt++)
#pragma unroll
        for (int half = 0; half < 2; half++) {
            int row = wm * 32 + mt * 16 + l4 + half * 8;
            __half* po = g_ao + ((size_t)b * C_ + hg * HD + row) * NPIX + ntile * 128;
#pragma unroll
            for (int nt = 0; nt < 4; nt++) {
                int col = wn * 32 + nt * 8 + l2;
                *(uint32_t*)(po + col) =
                    pack2h(__float2half_rn(acc[mt][nt][half * 2]),
                           __float2half_rn(acc[mt][nt][half * 2 + 1]));
            }
        }
}

// ---------------- launch ----------------
extern "C" void kernel_launch(void* const* d_in, const int* in_sizes, int n_in,
                              void* d_out, int out_size) {
    const float* x  = (const float*)d_in[0];
    const float* dw = (const float*)d_in[1];
    const float* qw = (const float*)d_in[2];
    const float* kw = (const float*)d_in[3];
    const float* vw = (const float*)d_in[4];
    const float* pw = (const float*)d_in[5];
    float* out = (float*)d_out;

    __half *yp, *aop, *whp;
    cudaGetSymbolAddress((void**)&yp,  g_y);
    cudaGetSymbolAddress((void**)&aop, g_ao);
    cudaGetSymbolAddress((void**)&whp, g_wh);

    cudaFuncSetAttribute(gemm1_kernel<0>, cudaFuncAttributeMaxDynamicSharedMemorySize, Q_SMEM);
    cudaFuncSetAttribute(gemm1_kernel<1>, cudaFuncAttributeMaxDynamicSharedMemorySize, Q_SMEM);
    cudaFuncSetAttribute(scores_kernel, cudaFuncAttributeMaxDynamicSharedMemorySize, SC_SMEM);
    cudaFuncSetAttribute(apply_kernel,  cudaFuncAttributeMaxDynamicSharedMemorySize, AP_SMEM);

    zero_kernel<<<16, 256>>>();                                          // 1
    dwconv_kernel<<<dim3(NPIX / 256, B_ * C_), 256>>>(x, dw);            // 2
    convert_w_kernel<<<4096, 256>>>(qw, kw, vw, pw);                     // 3
    // fused QKV GEMM, M=1536, CTA 128x128, 1-term (profiled slot)
    gemm1_kernel<0><<<dim3(NPIX / 128, 12, B_), 256, Q_SMEM>>>(whp, yp, nullptr); // 4
    scores_kernel<<<dim3(8, B_ * HEADS_), 256, SC_SMEM>>>();             // 5
    softmax_kernel<<<B_ * HEADS_, 256>>>();                              // 6
    apply_kernel<<<dim3(NPIX / 128, B_ * HEADS_), 256, AP_SMEM>>>();     // 7
    // proj GEMM: 1-term, CTA 128x128, weight rows [1536, 2048)
    gemm1_kernel<1><<<dim3(NPIX / 128, 4, B_), 256, Q_SMEM>>>(           // 8
        whp + 1536 * C_, aop, out);
}